// round 2
// baseline (speedup 1.0000x reference)
#include <cuda_runtime.h>
#include <math.h>
#include <stdint.h>

// Problem constants
#define BB 2
#define TT 4096
#define CC 2048
#define HH 16
#define DD 128
#define KK 4
#define NTOK (BB*TT)          // 8192 tokens
#define NTOT (BB*TT*CC)       // 16777216 elements

// ---------------- scratch (device globals: allocation-free) ----------------
__device__ float g_xc[NTOT];      // conv+silu output
__device__ float g_q [NTOT];
__device__ float g_k [NTOT];
__device__ float g_v [NTOT];      // v -> kv -> mem (in place)
__device__ float g_ig[NTOT];
__device__ float g_og[NTOT];
__device__ float g_o [NTOT];      // gated output before final GEMM
__device__ float g_gamma[NTOK*HH];

// ---------------- helpers ----------------
__device__ __forceinline__ float warp_sum(float v) {
#pragma unroll
    for (int o = 16; o; o >>= 1) v += __shfl_xor_sync(0xFFFFFFFFu, v, o);
    return v;
}
__device__ __forceinline__ float sigmoidf(float x) { return 1.f / (1.f + expf(-x)); }

// ---------------- causal depthwise conv (K=4, left pad 3) + SiLU -----------
__global__ void conv_silu_kernel(const float* __restrict__ x,
                                 const float* __restrict__ w,
                                 const float* __restrict__ b) {
    int idx = blockIdx.x * blockDim.x + threadIdx.x;
    if (idx >= NTOT) return;
    int c = idx & (CC - 1);
    int t = (idx / CC) & (TT - 1);
    float acc = b[c];
    const float* wc = w + c * KK;
#pragma unroll
    for (int j = 0; j < KK; j++) {
        int tt = t - (KK - 1) + j;
        if (tt >= 0) acc = fmaf(x[idx + (j - (KK - 1)) * CC], wc[j], acc);
    }
    g_xc[idx] = acc * sigmoidf(acc);
}

// ---------------- SGEMM: Y[N,M] = A[N,K] @ W[M,K]^T ------------------------
// BM=BN=128, BK=16, 256 threads, 8x8 per thread. EPI: 0=none, 1=sigmoid(+bias)
#define GBM 128
#define GBN 128
#define GBK 16

template <int EPI>
__global__ void __launch_bounds__(256)
gemm_nt_kernel(const float* __restrict__ A, const float* __restrict__ W,
               float* __restrict__ C, const float* __restrict__ bias, int Kdim) {
    __shared__ float As[GBK][GBM + 4];
    __shared__ float Bs[GBK][GBN + 4];

    const int tid = threadIdx.x;
    const int tx = tid & 15;     // 0..15 -> N-tile cols (M dim)
    const int ty = tid >> 4;     // 0..15 -> M-tile rows (N dim)
    const int bn = blockIdx.x * GBN;   // along M (output cols)
    const int bm = blockIdx.y * GBM;   // along N (output rows)

    float acc[8][8];
#pragma unroll
    for (int i = 0; i < 8; i++)
#pragma unroll
        for (int j = 0; j < 8; j++) acc[i][j] = 0.f;

    const int lr = tid >> 2;          // 0..63
    const int lk = (tid & 3) << 2;    // 0,4,8,12

    const float* Ap = A + (size_t)(bm + lr) * Kdim + lk;
    const float* Wp = W + (size_t)(bn + lr) * Kdim + lk;

    for (int k0 = 0; k0 < Kdim; k0 += GBK) {
        float4 a0 = *(const float4*)(Ap + k0);
        float4 a1 = *(const float4*)(Ap + (size_t)64 * Kdim + k0);
        float4 b0 = *(const float4*)(Wp + k0);
        float4 b1 = *(const float4*)(Wp + (size_t)64 * Kdim + k0);

        As[lk + 0][lr] = a0.x; As[lk + 1][lr] = a0.y; As[lk + 2][lr] = a0.z; As[lk + 3][lr] = a0.w;
        As[lk + 0][lr + 64] = a1.x; As[lk + 1][lr + 64] = a1.y; As[lk + 2][lr + 64] = a1.z; As[lk + 3][lr + 64] = a1.w;
        Bs[lk + 0][lr] = b0.x; Bs[lk + 1][lr] = b0.y; Bs[lk + 2][lr] = b0.z; Bs[lk + 3][lr] = b0.w;
        Bs[lk + 0][lr + 64] = b1.x; Bs[lk + 1][lr + 64] = b1.y; Bs[lk + 2][lr + 64] = b1.z; Bs[lk + 3][lr + 64] = b1.w;
        __syncthreads();

#pragma unroll
        for (int kk = 0; kk < GBK; kk++) {
            float ar[8], br[8];
#pragma unroll
            for (int i = 0; i < 8; i++) ar[i] = As[kk][ty * 8 + i];
#pragma unroll
            for (int j = 0; j < 8; j++) br[j] = Bs[kk][tx * 8 + j];
#pragma unroll
            for (int i = 0; i < 8; i++)
#pragma unroll
                for (int j = 0; j < 8; j++) acc[i][j] = fmaf(ar[i], br[j], acc[i][j]);
        }
        __syncthreads();
    }

#pragma unroll
    for (int i = 0; i < 8; i++) {
        size_t n = (size_t)(bm + ty * 8 + i);
#pragma unroll
        for (int j = 0; j < 8; j++) {
            int m = bn + tx * 8 + j;
            float v = acc[i][j];
            if (EPI == 1) v = sigmoidf(v + bias[m]);
            C[n * CC + m] = v;
        }
    }
}

// ---------------- gamma = sigmoid(xc @ gamma_w^T + gamma_b), [NTOK, H] -----
__global__ void gamma_kernel(const float* __restrict__ gw, const float* __restrict__ gb) {
    __shared__ float sx[CC];
    int n = blockIdx.x;
    const float* xr = g_xc + (size_t)n * CC;
    for (int i = threadIdx.x; i < CC; i += 128) sx[i] = xr[i];
    __syncthreads();
    int warp = threadIdx.x >> 5, lane = threadIdx.x & 31;
    for (int h = warp; h < HH; h += 4) {
        const float* w = gw + (size_t)h * CC;
        float s = 0.f;
        for (int k = lane; k < CC; k += 32) s = fmaf(sx[k], w[k], s);
        s = warp_sum(s);
        if (lane == 0) g_gamma[(size_t)n * HH + h] = sigmoidf(s + gb[h]);
    }
}

// ---------------- per-(token,head) L2 norm over D=128 (in place) -----------
__global__ void l2norm_kernel(float* __restrict__ p) {
    int gw = (blockIdx.x * blockDim.x + threadIdx.x) >> 5;
    int lane = threadIdx.x & 31;
    if (gw >= NTOK * HH) return;
    float4* row = (float4*)(p + (size_t)gw * DD);
    float4 a = row[lane];
    float ss = a.x * a.x + a.y * a.y + a.z * a.z + a.w * a.w;
    ss = warp_sum(ss);
    float inv = 1.f / fmaxf(sqrtf(ss), 1e-12f);
    a.x *= inv; a.y *= inv; a.z *= inv; a.w *= inv;
    row[lane] = a;
}

// ---------------- v LayerNorm over D (in place) -----------------------------
__global__ void vln_kernel(float* __restrict__ p, const float* __restrict__ g,
                           const float* __restrict__ b) {
    int gw = (blockIdx.x * blockDim.x + threadIdx.x) >> 5;
    int lane = threadIdx.x & 31;
    if (gw >= NTOK * HH) return;
    float4* row = (float4*)(p + (size_t)gw * DD);
    float4 a = row[lane];
    float s = a.x + a.y + a.z + a.w;
    float ss = a.x * a.x + a.y * a.y + a.z * a.z + a.w * a.w;
    s = warp_sum(s); ss = warp_sum(ss);
    float mean = s * (1.f / DD);
    float var = ss * (1.f / DD) - mean * mean;
    float r = rsqrtf(var + 1e-5f);
    int d = lane * 4;
    a.x = (a.x - mean) * r * g[d + 0] + b[d + 0];
    a.y = (a.y - mean) * r * g[d + 1] + b[d + 1];
    a.z = (a.z - mean) * r * g[d + 2] + b[d + 2];
    a.w = (a.w - mean) * r * g[d + 3] + b[d + 3];
    row[lane] = a;
}

// ---------------- kv = i_gate * k * v (into g_v) ---------------------------
__global__ void kvprod_kernel() {
    int idx = blockIdx.x * blockDim.x + threadIdx.x;
    if (idx >= NTOT / 4) return;
    float4 ig = ((const float4*)g_ig)[idx];
    float4 k  = ((const float4*)g_k)[idx];
    float4 v  = ((float4*)g_v)[idx];
    v.x *= ig.x * k.x; v.y *= ig.y * k.y; v.z *= ig.z * k.z; v.w *= ig.w * k.w;
    ((float4*)g_v)[idx] = v;
}

// ---------------- sequential decayed scan over T (in place on g_v) ---------
// grid: B*H blocks, 128 threads (d). mem_t = gamma_t*mem_{t-1} + kv_t
__global__ void scan_kernel() {
    int b = blockIdx.x / HH;
    int h = blockIdx.x % HH;
    int d = threadIdx.x;
    size_t idx = ((size_t)b * TT * HH + h) * DD + d;
    const float* gam = g_gamma + (size_t)b * TT * HH + h;
    float mem = 0.f;
#pragma unroll 4
    for (int t = 0; t < TT; t++) {
        float g = __ldg(gam + (size_t)t * HH);
        mem = fmaf(g, mem, g_v[idx]);
        g_v[idx] = mem;
        idx += (size_t)HH * DD;
    }
}

// ---------------- LN(mem)*q -> GroupNorm -> *og ----------------------------
__global__ void post_kernel(const float* __restrict__ mn_g, const float* __restrict__ mn_b,
                            const float* __restrict__ gn_g, const float* __restrict__ gn_b) {
    int row = (blockIdx.x * blockDim.x + threadIdx.x) >> 5;   // (b,t,h)
    int lane = threadIdx.x & 31;
    if (row >= NTOK * HH) return;
    size_t off = (size_t)row * DD + lane * 4;
    float4 m  = *(const float4*)(g_v + off);
    float4 q  = *(const float4*)(g_q + off);
    float4 og = *(const float4*)(g_og + off);

    // LayerNorm of mem over D
    float s = m.x + m.y + m.z + m.w;
    float ss = m.x * m.x + m.y * m.y + m.z * m.z + m.w * m.w;
    s = warp_sum(s); ss = warp_sum(ss);
    float mean = s * (1.f / DD);
    float var = ss * (1.f / DD) - mean * mean;
    float r = rsqrtf(var + 1e-5f);
    int d = lane * 4;
    float4 o1;
    o1.x = ((m.x - mean) * r * mn_g[d + 0] + mn_b[d + 0]) * q.x;
    o1.y = ((m.y - mean) * r * mn_g[d + 1] + mn_b[d + 1]) * q.y;
    o1.z = ((m.z - mean) * r * mn_g[d + 2] + mn_b[d + 2]) * q.z;
    o1.w = ((m.w - mean) * r * mn_g[d + 3] + mn_b[d + 3]) * q.w;

    // GroupNorm over the same D
    float s2 = o1.x + o1.y + o1.z + o1.w;
    float ss2 = o1.x * o1.x + o1.y * o1.y + o1.z * o1.z + o1.w * o1.w;
    s2 = warp_sum(s2); ss2 = warp_sum(ss2);
    float mean2 = s2 * (1.f / DD);
    float var2 = ss2 * (1.f / DD) - mean2 * mean2;
    float r2 = rsqrtf(var2 + 1e-5f);
    int c = (row % HH) * DD + d;
    float4 o;
    o.x = (((o1.x - mean2) * r2) * gn_g[c + 0] + gn_b[c + 0]) * og.x;
    o.y = (((o1.y - mean2) * r2) * gn_g[c + 1] + gn_b[c + 1]) * og.y;
    o.z = (((o1.z - mean2) * r2) * gn_g[c + 2] + gn_b[c + 2]) * og.z;
    o.w = (((o1.w - mean2) * r2) * gn_g[c + 3] + gn_b[c + 3]) * og.w;
    *(float4*)(g_o + off) = o;
}

// ---------------- launch ----------------------------------------------------
extern "C" void kernel_launch(void* const* d_in, const int* in_sizes, int n_in,
                              void* d_out, int out_size) {
    const float* x       = (const float*)d_in[0];
    const float* Wq      = (const float*)d_in[1];
    const float* Wk      = (const float*)d_in[2];
    const float* Wv      = (const float*)d_in[3];
    const float* Wo      = (const float*)d_in[4];
    const float* conv_w  = (const float*)d_in[5];
    const float* conv_b  = (const float*)d_in[6];
    const float* ig_w    = (const float*)d_in[7];
    const float* ig_b    = (const float*)d_in[8];
    const float* og_w    = (const float*)d_in[9];
    const float* og_b    = (const float*)d_in[10];
    const float* gamma_w = (const float*)d_in[11];
    const float* gamma_b = (const float*)d_in[12];
    const float* vn_g    = (const float*)d_in[13];
    const float* vn_b    = (const float*)d_in[14];
    const float* gn_g    = (const float*)d_in[15];
    const float* gn_b    = (const float*)d_in[16];
    const float* mn_g    = (const float*)d_in[17];
    const float* mn_b    = (const float*)d_in[18];
    float* out = (float*)d_out;

    float *p_xc, *p_q, *p_k, *p_v, *p_ig, *p_og, *p_o;
    cudaGetSymbolAddress((void**)&p_xc, g_xc);
    cudaGetSymbolAddress((void**)&p_q,  g_q);
    cudaGetSymbolAddress((void**)&p_k,  g_k);
    cudaGetSymbolAddress((void**)&p_v,  g_v);
    cudaGetSymbolAddress((void**)&p_ig, g_ig);
    cudaGetSymbolAddress((void**)&p_og, g_og);
    cudaGetSymbolAddress((void**)&p_o,  g_o);

    dim3 ggrid(CC / GBN, NTOK / GBM);   // (16, 64)

    conv_silu_kernel<<<NTOT / 256, 256>>>(x, conv_w, conv_b);

    gemm_nt_kernel<0><<<ggrid, 256>>>(x,    Wq,   p_q,  nullptr, CC);
    gemm_nt_kernel<0><<<ggrid, 256>>>(x,    Wk,   p_k,  nullptr, CC);
    gemm_nt_kernel<0><<<ggrid, 256>>>(x,    Wv,   p_v,  nullptr, CC);
    gemm_nt_kernel<1><<<ggrid, 256>>>(p_xc, ig_w, p_ig, ig_b,    CC);
    gemm_nt_kernel<1><<<ggrid, 256>>>(p_xc, og_w, p_og, og_b,    CC);

    gamma_kernel<<<NTOK, 128>>>(gamma_w, gamma_b);

    int nrows = NTOK * HH;                       // 131072 rows of 128
    int rblocks = nrows / 8;                     // 8 warps per 256-thread block
    l2norm_kernel<<<rblocks, 256>>>(p_q);
    l2norm_kernel<<<rblocks, 256>>>(p_k);
    vln_kernel<<<rblocks, 256>>>(p_v, vn_g, vn_b);

    kvprod_kernel<<<(NTOT / 4) / 256, 256>>>();

    scan_kernel<<<BB * HH, DD>>>();

    post_kernel<<<rblocks, 256>>>(mn_g, mn_b, gn_g, gn_b);

    gemm_nt_kernel<0><<<ggrid, 256>>>(p_o, Wo, out, nullptr, CC);
}

// round 4
// speedup vs baseline: 2.0315x; 2.0315x over previous
#include <cuda_runtime.h>
#include <cuda_bf16.h>
#include <math.h>
#include <stdint.h>

// Problem constants
#define BB 2
#define TT 4096
#define CC 2048
#define HH 16
#define DD 128
#define KK 4
#define NTOK (BB*TT)          // 8192 tokens
#define NTOT (BB*TT*CC)       // 16777216 elements

// ---------------- scratch (device globals: allocation-free) ----------------
__device__ float g_xc[NTOT];      // conv+silu output (fp32, feeds gamma GEMM)
__device__ float g_q [NTOT];
__device__ float g_k [NTOT];
__device__ float g_v [NTOT];      // v -> kv -> mem (in place)
__device__ float g_ig[NTOT];
__device__ float g_og[NTOT];
__device__ float g_o [NTOT];      // gated output before final GEMM
__device__ float g_gamma[NTOK*HH];

// bf16 hi/lo split buffers
__device__ __nv_bfloat16 g_xh[NTOT], g_xl[NTOT];   // x
__device__ __nv_bfloat16 g_ch[NTOT], g_cl[NTOT];   // xc
__device__ __nv_bfloat16 g_oh[NTOT], g_ol[NTOT];   // o
__device__ __nv_bfloat16 g_wh[6*CC*CC], g_wl[6*CC*CC]; // Wq,Wk,Wv,ig_w,og_w,Wo

// ---------------- helpers ----------------
__device__ __forceinline__ float warp_sum(float v) {
#pragma unroll
    for (int o = 16; o; o >>= 1) v += __shfl_xor_sync(0xFFFFFFFFu, v, o);
    return v;
}
__device__ __forceinline__ float sigmoidf(float x) { return 1.f / (1.f + expf(-x)); }

__device__ __forceinline__ uint32_t smem_u32(const void* p) {
    uint32_t a;
    asm("{ .reg .u64 t; cvta.to.shared.u64 t, %1; cvt.u32.u64 %0, t; }" : "=r"(a) : "l"(p));
    return a;
}
__device__ __forceinline__ void cp16(uint32_t dst, const void* src) {
    asm volatile("cp.async.cg.shared.global [%0], [%1], 16;" :: "r"(dst), "l"(src));
}
#define CP_COMMIT() asm volatile("cp.async.commit_group;" ::: "memory")
template <int N>
__device__ __forceinline__ void cp_wait() { asm volatile("cp.async.wait_group %0;" :: "n"(N) : "memory"); }

__device__ __forceinline__ void ldsm4(uint32_t* r, uint32_t addr) {
    asm volatile("ldmatrix.sync.aligned.m8n8.x4.shared.b16 {%0,%1,%2,%3}, [%4];"
                 : "=r"(r[0]), "=r"(r[1]), "=r"(r[2]), "=r"(r[3]) : "r"(addr));
}
__device__ __forceinline__ void mma_bf16(float* c, const uint32_t* a, const uint32_t* b) {
    asm volatile(
        "mma.sync.aligned.m16n8k16.row.col.f32.bf16.bf16.f32 "
        "{%0,%1,%2,%3}, {%4,%5,%6,%7}, {%8,%9}, {%0,%1,%2,%3};"
        : "+f"(c[0]), "+f"(c[1]), "+f"(c[2]), "+f"(c[3])
        : "r"(a[0]), "r"(a[1]), "r"(a[2]), "r"(a[3]), "r"(b[0]), "r"(b[1]));
}

// ---------------- hi/lo bf16 split conversion ----------------
__global__ void cvt_kernel(const float* __restrict__ s, __nv_bfloat16* __restrict__ h,
                           __nv_bfloat16* __restrict__ l, int n) {
    int i = blockIdx.x * blockDim.x + threadIdx.x;
    if (i >= n) return;
    float v = s[i];
    __nv_bfloat16 hi = __float2bfloat16(v);
    h[i] = hi;
    l[i] = __float2bfloat16(v - __bfloat162float(hi));
}

// ---------------- HMMA GEMM: C[8192,2048] = A[8192,K] @ W[2048,K]^T --------
// Tile 128x128, BK=32, 8 warps (4x2, each 32x64), 3-stage cp.async pipeline.
// 3 bf16 products per k-step: Ah*Bh + Ah*Bl + Al*Bh (fp32 accumulate).
#define ROWB   80                 // padded row stride bytes (32 bf16 + 8 pad)
#define TILEB  (128*ROWB)         // 10240 B per matrix tile
#define STAGEB (4*TILEB)          // Ah,Al,Bh,Bl per stage = 40960 B
#define STAGES 3
#define BKK    32
#define KTILES (CC/BKK)           // 64
#define GEMM_SMEM (STAGES*STAGEB) // 122880 B

template <int EPI>
__global__ void __launch_bounds__(256, 1)
gemm_hmma(const __nv_bfloat16* __restrict__ Ah, const __nv_bfloat16* __restrict__ Al,
          const __nv_bfloat16* __restrict__ Bh, const __nv_bfloat16* __restrict__ Bl,
          float* __restrict__ C, const float* __restrict__ bias)
{
    extern __shared__ char smem[];
    const uint32_t sb = smem_u32(smem);
    const int tid = threadIdx.x;
    const int lane = tid & 31;
    const int wid = tid >> 5;
    const int bm = blockIdx.y * 128;
    const int bn = blockIdx.x * 128;
    const int wm = (wid >> 1) * 32;   // warp M offset in tile
    const int wn = (wid & 1) * 64;    // warp N offset in tile

    float acc[2][8][4];
#pragma unroll
    for (int i = 0; i < 2; i++)
#pragma unroll
        for (int j = 0; j < 8; j++)
#pragma unroll
            for (int r = 0; r < 4; r++) acc[i][j][r] = 0.f;

    const __nv_bfloat16* gmat[4] = {Ah, Al, Bh, Bl};
    const int rowbase[4] = {bm, bm, bn, bn};

    // ldmatrix lane-address offsets (constant per thread)
    const uint32_t a_roff = (uint32_t)((lane & 15) * ROWB) + ((lane >> 4) << 4);
    const uint32_t b_roff = (uint32_t)((((lane & 7) | ((lane >> 4) << 3))) * ROWB)
                            + (((lane >> 3) & 1) << 4);

    // stage loader: 512 x 16B transfers per matrix, 2 per thread per matrix
    auto load_stage = [&](int s, int kt) {
        uint32_t base = sb + s * STAGEB;
        int k0 = kt * BKK;
#pragma unroll
        for (int m = 0; m < 4; m++) {
#pragma unroll
            for (int j = 0; j < 2; j++) {
                int u = tid + j * 256;          // 0..511
                int r = u >> 2, c = u & 3;      // row 0..127, 16B chunk 0..3
                cp16(base + m * TILEB + r * ROWB + c * 16,
                     gmat[m] + (size_t)(rowbase[m] + r) * CC + k0 + c * 8);
            }
        }
    };

    load_stage(0, 0); CP_COMMIT();
    load_stage(1, 1); CP_COMMIT();

    for (int kt = 0; kt < KTILES; kt++) {
        if (kt == KTILES - 1) cp_wait<0>(); else cp_wait<1>();
        __syncthreads();
        if (kt + 2 < KTILES) { load_stage((kt + 2) % STAGES, kt + 2); CP_COMMIT(); }

        const uint32_t st = sb + (kt % STAGES) * STAGEB;
        const uint32_t tAh = st, tAl = st + TILEB, tBh = st + 2*TILEB, tBl = st + 3*TILEB;
#pragma unroll
        for (int ks = 0; ks < 2; ks++) {
            uint32_t ao = (uint32_t)(wm * ROWB) + a_roff + (ks * 2) * 16;
            uint32_t ah[2][4], al[2][4];
            ldsm4(ah[0], tAh + ao);
            ldsm4(ah[1], tAh + ao + 16 * ROWB);
            ldsm4(al[0], tAl + ao);
            ldsm4(al[1], tAl + ao + 16 * ROWB);
            uint32_t bo = (uint32_t)(wn * ROWB) + b_roff + (ks * 2) * 16;
#pragma unroll
            for (int jj = 0; jj < 4; jj++) {
                uint32_t bh[4], bl[4];
                ldsm4(bh, tBh + bo + jj * 16 * ROWB);
                ldsm4(bl, tBl + bo + jj * 16 * ROWB);
#pragma unroll
                for (int i = 0; i < 2; i++) {
                    mma_bf16(acc[i][2*jj],   ah[i], bh);
                    mma_bf16(acc[i][2*jj+1], ah[i], bh + 2);
                    mma_bf16(acc[i][2*jj],   ah[i], bl);
                    mma_bf16(acc[i][2*jj+1], ah[i], bl + 2);
                    mma_bf16(acc[i][2*jj],   al[i], bh);
                    mma_bf16(acc[i][2*jj+1], al[i], bh + 2);
                }
            }
        }
    }

    // epilogue
    const int gr = lane >> 2, ti = lane & 3;
#pragma unroll
    for (int i = 0; i < 2; i++) {
        int m0 = bm + wm + i * 16 + gr;
#pragma unroll
        for (int j = 0; j < 8; j++) {
            int col = bn + wn + j * 8 + ti * 2;
            float2 v0 = make_float2(acc[i][j][0], acc[i][j][1]);
            float2 v1 = make_float2(acc[i][j][2], acc[i][j][3]);
            if (EPI == 1) {
                float b0 = bias[col], b1 = bias[col + 1];
                v0.x = sigmoidf(v0.x + b0); v0.y = sigmoidf(v0.y + b1);
                v1.x = sigmoidf(v1.x + b0); v1.y = sigmoidf(v1.y + b1);
            }
            *(float2*)(C + (size_t)m0 * CC + col) = v0;
            *(float2*)(C + (size_t)(m0 + 8) * CC + col) = v1;
        }
    }
}

// ---------------- causal depthwise conv (K=4, left pad 3) + SiLU -----------
__global__ void conv_silu_kernel(const float* __restrict__ x,
                                 const float* __restrict__ w,
                                 const float* __restrict__ b) {
    int idx = blockIdx.x * blockDim.x + threadIdx.x;
    if (idx >= NTOT) return;
    int c = idx & (CC - 1);
    int t = (idx / CC) & (TT - 1);
    float acc = b[c];
    const float* wc = w + c * KK;
#pragma unroll
    for (int j = 0; j < KK; j++) {
        int tt = t - (KK - 1) + j;
        if (tt >= 0) acc = fmaf(x[idx + (j - (KK - 1)) * CC], wc[j], acc);
    }
    g_xc[idx] = acc * sigmoidf(acc);
}

// ---------------- gamma = sigmoid(xc @ gamma_w^T + gamma_b), fp32 ----------
__global__ void gamma_kernel(const float* __restrict__ gw, const float* __restrict__ gb) {
    __shared__ float sx[CC];
    int n = blockIdx.x;
    const float* xr = g_xc + (size_t)n * CC;
    for (int i = threadIdx.x; i < CC; i += 128) sx[i] = xr[i];
    __syncthreads();
    int warp = threadIdx.x >> 5, lane = threadIdx.x & 31;
    for (int h = warp; h < HH; h += 4) {
        const float* w = gw + (size_t)h * CC;
        float s = 0.f;
        for (int k = lane; k < CC; k += 32) s = fmaf(sx[k], w[k], s);
        s = warp_sum(s);
        if (lane == 0) g_gamma[(size_t)n * HH + h] = sigmoidf(s + gb[h]);
    }
}

// ---------------- per-(token,head) L2 norm over D=128 (in place) -----------
__global__ void l2norm_kernel(float* __restrict__ p) {
    int gw = (blockIdx.x * blockDim.x + threadIdx.x) >> 5;
    int lane = threadIdx.x & 31;
    if (gw >= NTOK * HH) return;
    float4* row = (float4*)(p + (size_t)gw * DD);
    float4 a = row[lane];
    float ss = a.x * a.x + a.y * a.y + a.z * a.z + a.w * a.w;
    ss = warp_sum(ss);
    float inv = 1.f / fmaxf(sqrtf(ss), 1e-12f);
    a.x *= inv; a.y *= inv; a.z *= inv; a.w *= inv;
    row[lane] = a;
}

// ---------------- v LayerNorm over D (in place) -----------------------------
__global__ void vln_kernel(float* __restrict__ p, const float* __restrict__ g,
                           const float* __restrict__ b) {
    int gw = (blockIdx.x * blockDim.x + threadIdx.x) >> 5;
    int lane = threadIdx.x & 31;
    if (gw >= NTOK * HH) return;
    float4* row = (float4*)(p + (size_t)gw * DD);
    float4 a = row[lane];
    float s = a.x + a.y + a.z + a.w;
    float ss = a.x * a.x + a.y * a.y + a.z * a.z + a.w * a.w;
    s = warp_sum(s); ss = warp_sum(ss);
    float mean = s * (1.f / DD);
    float var = ss * (1.f / DD) - mean * mean;
    float r = rsqrtf(var + 1e-5f);
    int d = lane * 4;
    a.x = (a.x - mean) * r * g[d + 0] + b[d + 0];
    a.y = (a.y - mean) * r * g[d + 1] + b[d + 1];
    a.z = (a.z - mean) * r * g[d + 2] + b[d + 2];
    a.w = (a.w - mean) * r * g[d + 3] + b[d + 3];
    row[lane] = a;
}

// ---------------- kv = i_gate * k * v (into g_v) ---------------------------
__global__ void kvprod_kernel() {
    int idx = blockIdx.x * blockDim.x + threadIdx.x;
    if (idx >= NTOT / 4) return;
    float4 ig = ((const float4*)g_ig)[idx];
    float4 k  = ((const float4*)g_k)[idx];
    float4 v  = ((float4*)g_v)[idx];
    v.x *= ig.x * k.x; v.y *= ig.y * k.y; v.z *= ig.z * k.z; v.w *= ig.w * k.w;
    ((float4*)g_v)[idx] = v;
}

// ---------------- sequential decayed scan over T (in place on g_v) ---------
__global__ void scan_kernel() {
    int b = blockIdx.x / HH;
    int h = blockIdx.x % HH;
    int d = threadIdx.x;
    size_t idx = ((size_t)b * TT * HH + h) * DD + d;
    const float* gam = g_gamma + (size_t)b * TT * HH + h;
    float mem = 0.f;
#pragma unroll 4
    for (int t = 0; t < TT; t++) {
        float g = __ldg(gam + (size_t)t * HH);
        mem = fmaf(g, mem, g_v[idx]);
        g_v[idx] = mem;
        idx += (size_t)HH * DD;
    }
}

// ---------------- LN(mem)*q -> GroupNorm -> *og ----------------------------
__global__ void post_kernel(const float* __restrict__ mn_g, const float* __restrict__ mn_b,
                            const float* __restrict__ gn_g, const float* __restrict__ gn_b) {
    int row = (blockIdx.x * blockDim.x + threadIdx.x) >> 5;
    int lane = threadIdx.x & 31;
    if (row >= NTOK * HH) return;
    size_t off = (size_t)row * DD + lane * 4;
    float4 m  = *(const float4*)(g_v + off);
    float4 q  = *(const float4*)(g_q + off);
    float4 og = *(const float4*)(g_og + off);

    float s = m.x + m.y + m.z + m.w;
    float ss = m.x * m.x + m.y * m.y + m.z * m.z + m.w * m.w;
    s = warp_sum(s); ss = warp_sum(ss);
    float mean = s * (1.f / DD);
    float var = ss * (1.f / DD) - mean * mean;
    float r = rsqrtf(var + 1e-5f);
    int d = lane * 4;
    float4 o1;
    o1.x = ((m.x - mean) * r * mn_g[d + 0] + mn_b[d + 0]) * q.x;
    o1.y = ((m.y - mean) * r * mn_g[d + 1] + mn_b[d + 1]) * q.y;
    o1.z = ((m.z - mean) * r * mn_g[d + 2] + mn_b[d + 2]) * q.z;
    o1.w = ((m.w - mean) * r * mn_g[d + 3] + mn_b[d + 3]) * q.w;

    float s2 = o1.x + o1.y + o1.z + o1.w;
    float ss2 = o1.x * o1.x + o1.y * o1.y + o1.z * o1.z + o1.w * o1.w;
    s2 = warp_sum(s2); ss2 = warp_sum(ss2);
    float mean2 = s2 * (1.f / DD);
    float var2 = ss2 * (1.f / DD) - mean2 * mean2;
    float r2 = rsqrtf(var2 + 1e-5f);
    int c = (row % HH) * DD + d;
    float4 o;
    o.x = (((o1.x - mean2) * r2) * gn_g[c + 0] + gn_b[c + 0]) * og.x;
    o.y = (((o1.y - mean2) * r2) * gn_g[c + 1] + gn_b[c + 1]) * og.y;
    o.z = (((o1.z - mean2) * r2) * gn_g[c + 2] + gn_b[c + 2]) * og.z;
    o.w = (((o1.w - mean2) * r2) * gn_g[c + 3] + gn_b[c + 3]) * og.w;
    *(float4*)(g_o + off) = o;
}

// ---------------- launch ----------------------------------------------------
extern "C" void kernel_launch(void* const* d_in, const int* in_sizes, int n_in,
                              void* d_out, int out_size) {
    const float* x       = (const float*)d_in[0];
    const float* Wq      = (const float*)d_in[1];
    const float* Wk      = (const float*)d_in[2];
    const float* Wv      = (const float*)d_in[3];
    const float* Wo      = (const float*)d_in[4];
    const float* conv_w  = (const float*)d_in[5];
    const float* conv_b  = (const float*)d_in[6];
    const float* ig_w    = (const float*)d_in[7];
    const float* ig_b    = (const float*)d_in[8];
    const float* og_w    = (const float*)d_in[9];
    const float* og_b    = (const float*)d_in[10];
    const float* gamma_w = (const float*)d_in[11];
    const float* gamma_b = (const float*)d_in[12];
    const float* vn_g    = (const float*)d_in[13];
    const float* vn_b    = (const float*)d_in[14];
    const float* gn_g    = (const float*)d_in[15];
    const float* gn_b    = (const float*)d_in[16];
    const float* mn_g    = (const float*)d_in[17];
    const float* mn_b    = (const float*)d_in[18];
    float* out = (float*)d_out;

    float *p_xc, *p_q, *p_k, *p_v, *p_ig, *p_og, *p_o;
    cudaGetSymbolAddress((void**)&p_xc, g_xc);
    cudaGetSymbolAddress((void**)&p_q,  g_q);
    cudaGetSymbolAddress((void**)&p_k,  g_k);
    cudaGetSymbolAddress((void**)&p_v,  g_v);
    cudaGetSymbolAddress((void**)&p_ig, g_ig);
    cudaGetSymbolAddress((void**)&p_og, g_og);
    cudaGetSymbolAddress((void**)&p_o,  g_o);

    __nv_bfloat16 *p_xh, *p_xl, *p_ch, *p_cl, *p_oh, *p_ol, *p_wh, *p_wl;
    cudaGetSymbolAddress((void**)&p_xh, g_xh);
    cudaGetSymbolAddress((void**)&p_xl, g_xl);
    cudaGetSymbolAddress((void**)&p_ch, g_ch);
    cudaGetSymbolAddress((void**)&p_cl, g_cl);
    cudaGetSymbolAddress((void**)&p_oh, g_oh);
    cudaGetSymbolAddress((void**)&p_ol, g_ol);
    cudaGetSymbolAddress((void**)&p_wh, g_wh);
    cudaGetSymbolAddress((void**)&p_wl, g_wl);

    cudaFuncSetAttribute(gemm_hmma<0>, cudaFuncAttributeMaxDynamicSharedMemorySize, GEMM_SMEM);
    cudaFuncSetAttribute(gemm_hmma<1>, cudaFuncAttributeMaxDynamicSharedMemorySize, GEMM_SMEM);

    const int WSZ = CC * CC;   // 4M elems per weight matrix

    conv_silu_kernel<<<NTOT / 256, 256>>>(x, conv_w, conv_b);

    // hi/lo conversions
    cvt_kernel<<<NTOT / 256, 256>>>(x,    p_xh, p_xl, NTOT);
    cvt_kernel<<<NTOT / 256, 256>>>(p_xc, p_ch, p_cl, NTOT);
    cvt_kernel<<<WSZ / 256, 256>>>(Wq,   p_wh + 0*(size_t)WSZ, p_wl + 0*(size_t)WSZ, WSZ);
    cvt_kernel<<<WSZ / 256, 256>>>(Wk,   p_wh + 1*(size_t)WSZ, p_wl + 1*(size_t)WSZ, WSZ);
    cvt_kernel<<<WSZ / 256, 256>>>(Wv,   p_wh + 2*(size_t)WSZ, p_wl + 2*(size_t)WSZ, WSZ);
    cvt_kernel<<<WSZ / 256, 256>>>(ig_w, p_wh + 3*(size_t)WSZ, p_wl + 3*(size_t)WSZ, WSZ);
    cvt_kernel<<<WSZ / 256, 256>>>(og_w, p_wh + 4*(size_t)WSZ, p_wl + 4*(size_t)WSZ, WSZ);
    cvt_kernel<<<WSZ / 256, 256>>>(Wo,   p_wh + 5*(size_t)WSZ, p_wl + 5*(size_t)WSZ, WSZ);

    dim3 ggrid(CC / 128, NTOK / 128);   // (16, 64) = 1024 CTAs

    gemm_hmma<0><<<ggrid, 256, GEMM_SMEM>>>(p_xh, p_xl, p_wh + 0*(size_t)WSZ, p_wl + 0*(size_t)WSZ, p_q,  nullptr);
    gemm_hmma<0><<<ggrid, 256, GEMM_SMEM>>>(p_xh, p_xl, p_wh + 1*(size_t)WSZ, p_wl + 1*(size_t)WSZ, p_k,  nullptr);
    gemm_hmma<0><<<ggrid, 256, GEMM_SMEM>>>(p_xh, p_xl, p_wh + 2*(size_t)WSZ, p_wl + 2*(size_t)WSZ, p_v,  nullptr);
    gemm_hmma<1><<<ggrid, 256, GEMM_SMEM>>>(p_ch, p_cl, p_wh + 3*(size_t)WSZ, p_wl + 3*(size_t)WSZ, p_ig, ig_b);
    gemm_hmma<1><<<ggrid, 256, GEMM_SMEM>>>(p_ch, p_cl, p_wh + 4*(size_t)WSZ, p_wl + 4*(size_t)WSZ, p_og, og_b);

    gamma_kernel<<<NTOK, 128>>>(gamma_w, gamma_b);

    int nrows = NTOK * HH;                       // 131072 rows of 128
    int rblocks = nrows / 8;
    l2norm_kernel<<<rblocks, 256>>>(p_q);
    l2norm_kernel<<<rblocks, 256>>>(p_k);
    vln_kernel<<<rblocks, 256>>>(p_v, vn_g, vn_b);

    kvprod_kernel<<<(NTOT / 4) / 256, 256>>>();

    scan_kernel<<<BB * HH, DD>>>();

    post_kernel<<<rblocks, 256>>>(mn_g, mn_b, gn_g, gn_b);

    cvt_kernel<<<NTOT / 256, 256>>>(p_o, p_oh, p_ol, NTOT);
    gemm_hmma<0><<<ggrid, 256, GEMM_SMEM>>>(p_oh, p_ol, p_wh + 5*(size_t)WSZ, p_wl + 5*(size_t)WSZ, out, nullptr);
}

// round 6
// speedup vs baseline: 2.2476x; 1.1064x over previous
#include <cuda_runtime.h>
#include <cuda_bf16.h>
#include <math.h>
#include <stdint.h>

// Problem constants
#define BB 2
#define TT 4096
#define CC 2048
#define HH 16
#define DD 128
#define KK 4
#define NTOK (BB*TT)          // 8192 tokens
#define NTOT (BB*TT*CC)       // 16777216 elements

// ---------------- scratch (device globals: allocation-free) ----------------
__device__ float g_xc[NTOT];      // conv+silu output (fp32, feeds gamma GEMM)
__device__ float g_q [NTOT];
__device__ float g_k [NTOT];
__device__ float g_v [NTOT];      // v -> kv -> mem (in place)
__device__ float g_ig[NTOT];
__device__ float g_og[NTOT];
__device__ float g_gamma[NTOK*HH];

// bf16 hi/lo split buffers
__device__ __nv_bfloat16 g_xh[NTOT], g_xl[NTOT];   // x
__device__ __nv_bfloat16 g_ch[NTOT], g_cl[NTOT];   // xc
__device__ __nv_bfloat16 g_oh[NTOT], g_ol[NTOT];   // o (gated output)
__device__ __nv_bfloat16 g_wh[6*CC*CC], g_wl[6*CC*CC]; // Wq,Wk,Wv,ig_w,og_w,Wo

// ---------------- helpers ----------------
__device__ __forceinline__ float warp_sum(float v) {
#pragma unroll
    for (int o = 16; o; o >>= 1) v += __shfl_xor_sync(0xFFFFFFFFu, v, o);
    return v;
}
__device__ __forceinline__ float sigmoidf(float x) { return 1.f / (1.f + expf(-x)); }

__device__ __forceinline__ uint32_t smem_u32(const void* p) {
    uint32_t a;
    asm("{ .reg .u64 t; cvta.to.shared.u64 t, %1; cvt.u32.u64 %0, t; }" : "=r"(a) : "l"(p));
    return a;
}
__device__ __forceinline__ void cp16(uint32_t dst, const void* src) {
    asm volatile("cp.async.cg.shared.global [%0], [%1], 16;" :: "r"(dst), "l"(src));
}
#define CP_COMMIT() asm volatile("cp.async.commit_group;" ::: "memory")
template <int N>
__device__ __forceinline__ void cp_wait() { asm volatile("cp.async.wait_group %0;" :: "n"(N) : "memory"); }

__device__ __forceinline__ void ldsm4(uint32_t* r, uint32_t addr) {
    asm volatile("ldmatrix.sync.aligned.m8n8.x4.shared.b16 {%0,%1,%2,%3}, [%4];"
                 : "=r"(r[0]), "=r"(r[1]), "=r"(r[2]), "=r"(r[3]) : "r"(addr));
}
__device__ __forceinline__ void mma_bf16(float* c, const uint32_t* a, const uint32_t* b) {
    asm volatile(
        "mma.sync.aligned.m16n8k16.row.col.f32.bf16.bf16.f32 "
        "{%0,%1,%2,%3}, {%4,%5,%6,%7}, {%8,%9}, {%0,%1,%2,%3};"
        : "+f"(c[0]), "+f"(c[1]), "+f"(c[2]), "+f"(c[3])
        : "r"(a[0]), "r"(a[1]), "r"(a[2]), "r"(a[3]), "r"(b[0]), "r"(b[1]));
}

// ---------------- hi/lo bf16 split conversion ----------------
__global__ void cvt_kernel(const float* __restrict__ s, __nv_bfloat16* __restrict__ h,
                           __nv_bfloat16* __restrict__ l, int n) {
    int i = blockIdx.x * blockDim.x + threadIdx.x;
    if (i >= n) return;
    float v = s[i];
    __nv_bfloat16 hi = __float2bfloat16(v);
    h[i] = hi;
    l[i] = __float2bfloat16(v - __bfloat162float(hi));
}

// ---------------- HMMA GEMM: C[8192,2048] = A[8192,K] @ W[2048,K]^T --------
// CTA tile 256x128, BK=32, 8 warps (4x2), warp tile 64x64.
// Smem row = 128B packed [hi 64B | lo 64B], SW128-style XOR swizzle
// (chunk ^= row&7) -> conflict-free cp.async stores and ldmatrix loads.
// 3 bf16 products per k-step: Ah*Bh + Ah*Bl + Al*Bh (fp32 accumulate).
#define BKK     32
#define KT16    (CC/16)            // 128 k16 steps
#define ATILE_B (256*128)          // 32768
#define BTILE_B (128*128)          // 16384
#define STAGEB  (ATILE_B+BTILE_B)  // 49152
#define STAGES  3
#define KTILES  (CC/BKK)           // 64
#define GEMM_SMEM (STAGES*STAGEB)  // 147456

template <int EPI>
__global__ void __launch_bounds__(256, 1)
gemm_hmma(const __nv_bfloat16* __restrict__ Ah, const __nv_bfloat16* __restrict__ Al,
          const __nv_bfloat16* __restrict__ Bh, const __nv_bfloat16* __restrict__ Bl,
          float* __restrict__ C, const float* __restrict__ bias)
{
    extern __shared__ char smem[];
    const uint32_t sb = smem_u32(smem);
    const int tid = threadIdx.x;
    const int lane = tid & 31;
    const int wid = tid >> 5;
    const int bm = blockIdx.y * 256;
    const int bn = blockIdx.x * 128;
    const int wm = (wid >> 1) * 64;   // warp M offset in tile (0..192)
    const int wn = (wid & 1) * 64;    // warp N offset in tile (0,64)

    float acc[4][8][4];
#pragma unroll
    for (int i = 0; i < 4; i++)
#pragma unroll
        for (int j = 0; j < 8; j++)
#pragma unroll
            for (int r = 0; r < 4; r++) acc[i][j][r] = 0.f;

    // per-thread ldmatrix address components
    const uint32_t xm = (uint32_t)((lane & 7) << 4);            // swizzle xor mask
    const int arow = lane & 15;
    const uint32_t ahalf = (uint32_t)((lane >> 4) << 4);        // 0 or 16
    const int brow = (lane & 7) | ((lane >> 4) << 3);
    const uint32_t bhalf = (uint32_t)(((lane >> 3) & 1) << 4);  // 0 or 16

    // stage loader: A 2048 + B 1024 16B units, 12 per thread
    auto load_stage = [&](int s, int kt) {
        uint32_t base = sb + s * STAGEB;
        int k0 = kt * BKK;
#pragma unroll
        for (int i = 0; i < 8; i++) {
            int u = tid + i * 256;
            int r = u >> 3, c = u & 7;
            const __nv_bfloat16* src = ((c & 4) ? Al : Ah) + (size_t)(bm + r) * CC + k0 + (c & 3) * 8;
            cp16(base + r * 128 + ((uint32_t)(c * 16) ^ (uint32_t)((r & 7) << 4)), src);
        }
#pragma unroll
        for (int i = 0; i < 4; i++) {
            int u = tid + i * 256;
            int r = u >> 3, c = u & 7;
            const __nv_bfloat16* src = ((c & 4) ? Bl : Bh) + (size_t)(bn + r) * CC + k0 + (c & 3) * 8;
            cp16(base + ATILE_B + r * 128 + ((uint32_t)(c * 16) ^ (uint32_t)((r & 7) << 4)), src);
        }
    };

    load_stage(0, 0); CP_COMMIT();
    load_stage(1, 1); CP_COMMIT();

    for (int kt = 0; kt < KTILES; kt++) {
        if (kt == KTILES - 1) cp_wait<0>(); else cp_wait<1>();
        __syncthreads();
        if (kt + 2 < KTILES) { load_stage((kt + 2) % STAGES, kt + 2); CP_COMMIT(); }

        const uint32_t st = sb + (kt % STAGES) * STAGEB;
        const uint32_t aBase = st + (uint32_t)((wm + arow) * 128);
        const uint32_t bBase = st + ATILE_B + (uint32_t)((wn + brow) * 128);
#pragma unroll
        for (int ks = 0; ks < 2; ks++) {
            uint32_t ah[4][4], al[4][4];
            const uint32_t aoff_h = ((uint32_t)(ks * 32) + ahalf) ^ xm;
            const uint32_t aoff_l = ((uint32_t)(ks * 32) + ahalf + 64) ^ xm;
#pragma unroll
            for (int mi = 0; mi < 4; mi++) {
                ldsm4(ah[mi], aBase + mi * 2048 + aoff_h);
                ldsm4(al[mi], aBase + mi * 2048 + aoff_l);
            }
            const uint32_t boff_h = ((uint32_t)(ks * 32) + bhalf) ^ xm;
            const uint32_t boff_l = ((uint32_t)(ks * 32) + bhalf + 64) ^ xm;
#pragma unroll
            for (int jj = 0; jj < 4; jj++) {
                uint32_t bh[4], bl[4];
                ldsm4(bh, bBase + jj * 2048 + boff_h);
                ldsm4(bl, bBase + jj * 2048 + boff_l);
#pragma unroll
                for (int mi = 0; mi < 4; mi++) {
                    mma_bf16(acc[mi][2*jj],   ah[mi], bh);
                    mma_bf16(acc[mi][2*jj+1], ah[mi], bh + 2);
                    mma_bf16(acc[mi][2*jj],   ah[mi], bl);
                    mma_bf16(acc[mi][2*jj+1], ah[mi], bl + 2);
                    mma_bf16(acc[mi][2*jj],   al[mi], bh);
                    mma_bf16(acc[mi][2*jj+1], al[mi], bh + 2);
                }
            }
        }
    }

    // epilogue
    const int gr = lane >> 2, ti = lane & 3;
#pragma unroll
    for (int mi = 0; mi < 4; mi++) {
        int m0 = bm + wm + mi * 16 + gr;
#pragma unroll
        for (int j = 0; j < 8; j++) {
            int col = bn + wn + j * 8 + ti * 2;
            float2 v0 = make_float2(acc[mi][j][0], acc[mi][j][1]);
            float2 v1 = make_float2(acc[mi][j][2], acc[mi][j][3]);
            if (EPI == 1) {
                float b0 = bias[col], b1 = bias[col + 1];
                v0.x = sigmoidf(v0.x + b0); v0.y = sigmoidf(v0.y + b1);
                v1.x = sigmoidf(v1.x + b0); v1.y = sigmoidf(v1.y + b1);
            }
            *(float2*)(C + (size_t)m0 * CC + col) = v0;
            *(float2*)(C + (size_t)(m0 + 8) * CC + col) = v1;
        }
    }
}

// ---------------- causal depthwise conv (K=4) + SiLU + hi/lo split ---------
__global__ void conv_silu_kernel(const float* __restrict__ x,
                                 const float* __restrict__ w,
                                 const float* __restrict__ b) {
    int idx = blockIdx.x * blockDim.x + threadIdx.x;
    if (idx >= NTOT) return;
    int c = idx & (CC - 1);
    int t = (idx / CC) & (TT - 1);
    float acc = b[c];
    const float* wc = w + c * KK;
#pragma unroll
    for (int j = 0; j < KK; j++) {
        int tt = t - (KK - 1) + j;
        if (tt >= 0) acc = fmaf(x[idx + (j - (KK - 1)) * CC], wc[j], acc);
    }
    float y = acc * sigmoidf(acc);
    g_xc[idx] = y;
    __nv_bfloat16 hi = __float2bfloat16(y);
    g_ch[idx] = hi;
    g_cl[idx] = __float2bfloat16(y - __bfloat162float(hi));
}

// ---------------- gamma = sigmoid(xc @ gamma_w^T + gamma_b), fp32 ----------
__global__ void gamma_kernel(const float* __restrict__ gw, const float* __restrict__ gb) {
    __shared__ float sx[CC];
    int n = blockIdx.x;
    const float* xr = g_xc + (size_t)n * CC;
    for (int i = threadIdx.x; i < CC; i += 128) sx[i] = xr[i];
    __syncthreads();
    int warp = threadIdx.x >> 5, lane = threadIdx.x & 31;
    for (int h = warp; h < HH; h += 4) {
        const float* w = gw + (size_t)h * CC;
        float s = 0.f;
        for (int k = lane; k < CC; k += 32) s = fmaf(sx[k], w[k], s);
        s = warp_sum(s);
        if (lane == 0) g_gamma[(size_t)n * HH + h] = sigmoidf(s + gb[h]);
    }
}

// ---------------- per-(token,head) L2 norm over D=128 (in place) -----------
__global__ void l2norm_kernel(float* __restrict__ p) {
    int gw = (blockIdx.x * blockDim.x + threadIdx.x) >> 5;
    int lane = threadIdx.x & 31;
    if (gw >= NTOK * HH) return;
    float4* row = (float4*)(p + (size_t)gw * DD);
    float4 a = row[lane];
    float ss = a.x * a.x + a.y * a.y + a.z * a.z + a.w * a.w;
    ss = warp_sum(ss);
    float inv = 1.f / fmaxf(sqrtf(ss), 1e-12f);
    a.x *= inv; a.y *= inv; a.z *= inv; a.w *= inv;
    row[lane] = a;
}

// ---------------- fused: v LayerNorm + kv = ig * k * vn (in place on g_v) --
__global__ void vln_kv_kernel(const float* __restrict__ g, const float* __restrict__ b) {
    int gw = (blockIdx.x * blockDim.x + threadIdx.x) >> 5;
    int lane = threadIdx.x & 31;
    if (gw >= NTOK * HH) return;
    size_t off = (size_t)gw * DD + lane * 4;
    float4 a = *(float4*)(g_v + off);
    float s = a.x + a.y + a.z + a.w;
    float ss = a.x * a.x + a.y * a.y + a.z * a.z + a.w * a.w;
    s = warp_sum(s); ss = warp_sum(ss);
    float mean = s * (1.f / DD);
    float var = ss * (1.f / DD) - mean * mean;
    float r = rsqrtf(var + 1e-5f);
    int d = lane * 4;
    float4 ig = *(const float4*)(g_ig + off);
    float4 k  = *(const float4*)(g_k + off);
    a.x = ((a.x - mean) * r * g[d + 0] + b[d + 0]) * ig.x * k.x;
    a.y = ((a.y - mean) * r * g[d + 1] + b[d + 1]) * ig.y * k.y;
    a.z = ((a.z - mean) * r * g[d + 2] + b[d + 2]) * ig.z * k.z;
    a.w = ((a.w - mean) * r * g[d + 3] + b[d + 3]) * ig.w * k.w;
    *(float4*)(g_v + off) = a;
}

// ---------------- sequential decayed scan over T (in place on g_v) ---------
__global__ void scan_kernel() {
    int b = blockIdx.x / HH;
    int h = blockIdx.x % HH;
    int d = threadIdx.x;
    size_t idx = ((size_t)b * TT * HH + h) * DD + d;
    const float* gam = g_gamma + (size_t)b * TT * HH + h;
    float mem = 0.f;
#pragma unroll 4
    for (int t = 0; t < TT; t++) {
        float g = __ldg(gam + (size_t)t * HH);
        mem = fmaf(g, mem, g_v[idx]);
        g_v[idx] = mem;
        idx += (size_t)HH * DD;
    }
}

// ---------------- LN(mem)*q -> GroupNorm -> *og -> hi/lo split -------------
__global__ void post_kernel(const float* __restrict__ mn_g, const float* __restrict__ mn_b,
                            const float* __restrict__ gn_g, const float* __restrict__ gn_b) {
    int row = (blockIdx.x * blockDim.x + threadIdx.x) >> 5;
    int lane = threadIdx.x & 31;
    if (row >= NTOK * HH) return;
    size_t off = (size_t)row * DD + lane * 4;
    float4 m  = *(const float4*)(g_v + off);
    float4 q  = *(const float4*)(g_q + off);
    float4 og = *(const float4*)(g_og + off);

    float s = m.x + m.y + m.z + m.w;
    float ss = m.x * m.x + m.y * m.y + m.z * m.z + m.w * m.w;
    s = warp_sum(s); ss = warp_sum(ss);
    float mean = s * (1.f / DD);
    float var = ss * (1.f / DD) - mean * mean;
    float r = rsqrtf(var + 1e-5f);
    int d = lane * 4;
    float4 o1;
    o1.x = ((m.x - mean) * r * mn_g[d + 0] + mn_b[d + 0]) * q.x;
    o1.y = ((m.y - mean) * r * mn_g[d + 1] + mn_b[d + 1]) * q.y;
    o1.z = ((m.z - mean) * r * mn_g[d + 2] + mn_b[d + 2]) * q.z;
    o1.w = ((m.w - mean) * r * mn_g[d + 3] + mn_b[d + 3]) * q.w;

    float s2 = o1.x + o1.y + o1.z + o1.w;
    float ss2 = o1.x * o1.x + o1.y * o1.y + o1.z * o1.z + o1.w * o1.w;
    s2 = warp_sum(s2); ss2 = warp_sum(ss2);
    float mean2 = s2 * (1.f / DD);
    float var2 = ss2 * (1.f / DD) - mean2 * mean2;
    float r2 = rsqrtf(var2 + 1e-5f);
    int c = (row % HH) * DD + d;
    float ov[4];
    ov[0] = (((o1.x - mean2) * r2) * gn_g[c + 0] + gn_b[c + 0]) * og.x;
    ov[1] = (((o1.y - mean2) * r2) * gn_g[c + 1] + gn_b[c + 1]) * og.y;
    ov[2] = (((o1.z - mean2) * r2) * gn_g[c + 2] + gn_b[c + 2]) * og.z;
    ov[3] = (((o1.w - mean2) * r2) * gn_g[c + 3] + gn_b[c + 3]) * og.w;
#pragma unroll
    for (int j = 0; j < 4; j++) {
        __nv_bfloat16 hi = __float2bfloat16(ov[j]);
        g_oh[off + j] = hi;
        g_ol[off + j] = __float2bfloat16(ov[j] - __bfloat162float(hi));
    }
}

// ---------------- launch ----------------------------------------------------
extern "C" void kernel_launch(void* const* d_in, const int* in_sizes, int n_in,
                              void* d_out, int out_size) {
    const float* x       = (const float*)d_in[0];
    const float* Wq      = (const float*)d_in[1];
    const float* Wk      = (const float*)d_in[2];
    const float* Wv      = (const float*)d_in[3];
    const float* Wo      = (const float*)d_in[4];
    const float* conv_w  = (const float*)d_in[5];
    const float* conv_b  = (const float*)d_in[6];
    const float* ig_w    = (const float*)d_in[7];
    const float* ig_b    = (const float*)d_in[8];
    const float* og_w    = (const float*)d_in[9];
    const float* og_b    = (const float*)d_in[10];
    const float* gamma_w = (const float*)d_in[11];
    const float* gamma_b = (const float*)d_in[12];
    const float* vn_g    = (const float*)d_in[13];
    const float* vn_b    = (const float*)d_in[14];
    const float* gn_g    = (const float*)d_in[15];
    const float* gn_b    = (const float*)d_in[16];
    const float* mn_g    = (const float*)d_in[17];
    const float* mn_b    = (const float*)d_in[18];
    float* out = (float*)d_out;

    float *p_q, *p_k, *p_v, *p_ig, *p_og;
    cudaGetSymbolAddress((void**)&p_q,  g_q);
    cudaGetSymbolAddress((void**)&p_k,  g_k);
    cudaGetSymbolAddress((void**)&p_v,  g_v);
    cudaGetSymbolAddress((void**)&p_ig, g_ig);
    cudaGetSymbolAddress((void**)&p_og, g_og);

    __nv_bfloat16 *p_xh, *p_xl, *p_ch, *p_cl, *p_oh, *p_ol, *p_wh, *p_wl;
    cudaGetSymbolAddress((void**)&p_xh, g_xh);
    cudaGetSymbolAddress((void**)&p_xl, g_xl);
    cudaGetSymbolAddress((void**)&p_ch, g_ch);
    cudaGetSymbolAddress((void**)&p_cl, g_cl);
    cudaGetSymbolAddress((void**)&p_oh, g_oh);
    cudaGetSymbolAddress((void**)&p_ol, g_ol);
    cudaGetSymbolAddress((void**)&p_wh, g_wh);
    cudaGetSymbolAddress((void**)&p_wl, g_wl);

    cudaFuncSetAttribute(gemm_hmma<0>, cudaFuncAttributeMaxDynamicSharedMemorySize, GEMM_SMEM);
    cudaFuncSetAttribute(gemm_hmma<1>, cudaFuncAttributeMaxDynamicSharedMemorySize, GEMM_SMEM);

    const int WSZ = CC * CC;   // 4M elems per weight matrix

    conv_silu_kernel<<<NTOT / 256, 256>>>(x, conv_w, conv_b);

    cvt_kernel<<<NTOT / 256, 256>>>(x, p_xh, p_xl, NTOT);
    cvt_kernel<<<WSZ / 256, 256>>>(Wq,   p_wh + 0*(size_t)WSZ, p_wl + 0*(size_t)WSZ, WSZ);
    cvt_kernel<<<WSZ / 256, 256>>>(Wk,   p_wh + 1*(size_t)WSZ, p_wl + 1*(size_t)WSZ, WSZ);
    cvt_kernel<<<WSZ / 256, 256>>>(Wv,   p_wh + 2*(size_t)WSZ, p_wl + 2*(size_t)WSZ, WSZ);
    cvt_kernel<<<WSZ / 256, 256>>>(ig_w, p_wh + 3*(size_t)WSZ, p_wl + 3*(size_t)WSZ, WSZ);
    cvt_kernel<<<WSZ / 256, 256>>>(og_w, p_wh + 4*(size_t)WSZ, p_wl + 4*(size_t)WSZ, WSZ);
    cvt_kernel<<<WSZ / 256, 256>>>(Wo,   p_wh + 5*(size_t)WSZ, p_wl + 5*(size_t)WSZ, WSZ);

    dim3 ggrid(CC / 128, NTOK / 256);   // (16, 32) = 512 CTAs

    gemm_hmma<0><<<ggrid, 256, GEMM_SMEM>>>(p_xh, p_xl, p_wh + 0*(size_t)WSZ, p_wl + 0*(size_t)WSZ, p_q,  nullptr);
    gemm_hmma<0><<<ggrid, 256, GEMM_SMEM>>>(p_xh, p_xl, p_wh + 1*(size_t)WSZ, p_wl + 1*(size_t)WSZ, p_k,  nullptr);
    gemm_hmma<0><<<ggrid, 256, GEMM_SMEM>>>(p_xh, p_xl, p_wh + 2*(size_t)WSZ, p_wl + 2*(size_t)WSZ, p_v,  nullptr);
    gemm_hmma<1><<<ggrid, 256, GEMM_SMEM>>>(p_ch, p_cl, p_wh + 3*(size_t)WSZ, p_wl + 3*(size_t)WSZ, p_ig, ig_b);
    gemm_hmma<1><<<ggrid, 256, GEMM_SMEM>>>(p_ch, p_cl, p_wh + 4*(size_t)WSZ, p_wl + 4*(size_t)WSZ, p_og, og_b);

    gamma_kernel<<<NTOK, 128>>>(gamma_w, gamma_b);

    int nrows = NTOK * HH;                       // 131072 rows of 128
    int rblocks = nrows / 8;
    l2norm_kernel<<<rblocks, 256>>>(p_q);
    l2norm_kernel<<<rblocks, 256>>>(p_k);
    vln_kv_kernel<<<rblocks, 256>>>(vn_g, vn_b);

    scan_kernel<<<BB * HH, DD>>>();

    post_kernel<<<rblocks, 256>>>(mn_g, mn_b, gn_g, gn_b);

    gemm_hmma<0><<<ggrid, 256, GEMM_SMEM>>>(p_oh, p_ol, p_wh + 5*(size_t)WSZ, p_wl + 5*(size_t)WSZ, out, nullptr);
}

// round 7
// speedup vs baseline: 3.5490x; 1.5790x over previous
#include <cuda_runtime.h>
#include <cuda_fp16.h>
#include <math.h>
#include <stdint.h>

// Problem constants
#define BB 2
#define TT 4096
#define CC 2048
#define HH 16
#define DD 128
#define KK 4
#define NTOK (BB*TT)          // 8192 tokens
#define NTOT (BB*TT*CC)       // 16777216 elements
#define NCH  32               // scan chunks
#define CHL  (TT/NCH)         // 128 timesteps per chunk

// ---------------- scratch (device globals: allocation-free) ----------------
__device__ float g_xc[NTOT];      // conv+silu output (fp32, feeds gamma GEMM)
__device__ float g_q [NTOT];
__device__ float g_k [NTOT];
__device__ float g_v [NTOT];      // v -> kv -> local mem (in place)
__device__ float g_ig[NTOT];
__device__ float g_og[NTOT];
__device__ float g_gamma[NTOK*HH];
__device__ float g_cumG[BB*HH*TT];          // per-chunk cumulative gamma
__device__ float g_carry[BB*HH*NCH*DD];     // chunk-final local mem
__device__ float g_prefix[BB*HH*NCH*DD];    // incoming prefix per chunk

// fp16 buffers (A-side: hi only; weights: hi+lo)
__device__ __half g_xh[NTOT];               // x (hi)
__device__ __half g_ch[NTOT];               // xc (hi)
__device__ __half g_oh[NTOT];               // gated output (hi)
__device__ __half g_wh[6*CC*CC], g_wl[6*CC*CC]; // Wq,Wk,Wv,ig_w,og_w,Wo

// ---------------- helpers ----------------
__device__ __forceinline__ float warp_sum(float v) {
#pragma unroll
    for (int o = 16; o; o >>= 1) v += __shfl_xor_sync(0xFFFFFFFFu, v, o);
    return v;
}
__device__ __forceinline__ float sigmoidf(float x) { return 1.f / (1.f + expf(-x)); }

__device__ __forceinline__ uint32_t smem_u32(const void* p) {
    uint32_t a;
    asm("{ .reg .u64 t; cvta.to.shared.u64 t, %1; cvt.u32.u64 %0, t; }" : "=r"(a) : "l"(p));
    return a;
}
__device__ __forceinline__ void cp16(uint32_t dst, const void* src) {
    asm volatile("cp.async.cg.shared.global [%0], [%1], 16;" :: "r"(dst), "l"(src));
}
#define CP_COMMIT() asm volatile("cp.async.commit_group;" ::: "memory")
template <int N>
__device__ __forceinline__ void cp_wait() { asm volatile("cp.async.wait_group %0;" :: "n"(N) : "memory"); }

__device__ __forceinline__ void ldsm4(uint32_t* r, uint32_t addr) {
    asm volatile("ldmatrix.sync.aligned.m8n8.x4.shared.b16 {%0,%1,%2,%3}, [%4];"
                 : "=r"(r[0]), "=r"(r[1]), "=r"(r[2]), "=r"(r[3]) : "r"(addr));
}
__device__ __forceinline__ void mma_f16(float* c, const uint32_t* a, const uint32_t* b) {
    asm volatile(
        "mma.sync.aligned.m16n8k16.row.col.f32.f16.f16.f32 "
        "{%0,%1,%2,%3}, {%4,%5,%6,%7}, {%8,%9}, {%0,%1,%2,%3};"
        : "+f"(c[0]), "+f"(c[1]), "+f"(c[2]), "+f"(c[3])
        : "r"(a[0]), "r"(a[1]), "r"(a[2]), "r"(a[3]), "r"(b[0]), "r"(b[1]));
}

// ---------------- conversions ----------------
__global__ void cvt_h_kernel(const float* __restrict__ s, __half* __restrict__ h, int n) {
    int i = blockIdx.x * blockDim.x + threadIdx.x;
    if (i >= n) return;
    h[i] = __float2half(s[i]);
}

// split all 6 weight matrices in one launch
__global__ void cvt_w_kernel(const float* __restrict__ w0, const float* __restrict__ w1,
                             const float* __restrict__ w2, const float* __restrict__ w3,
                             const float* __restrict__ w4, const float* __restrict__ w5) {
    int i = blockIdx.x * blockDim.x + threadIdx.x;           // 0 .. 6*WSZ-1
    const int WSZ = CC * CC;
    int j = i / WSZ, r = i - j * WSZ;
    const float* src = j == 0 ? w0 : j == 1 ? w1 : j == 2 ? w2 : j == 3 ? w3 : j == 4 ? w4 : w5;
    float v = src[r];
    __half hi = __float2half(v);
    g_wh[i] = hi;
    g_wl[i] = __float2half(v - __half2float(hi));
}

// ---------------- fp16 HMMA GEMM (2-product): C = A @ W^T -------------------
// CTA tile 256x128, BK=32, 8 warps (4x2), warp tile 64x64, 4-stage cp.async.
// A: hi-only fp16, rows of 64B data + 16B pad (ROWA=80), no swizzle.
// B: [hi 64B | lo 64B] packed 128B rows, XOR swizzle (chunk ^= row&7).
// Products per k16: Ah*Bh + Ah*Bl (fp32 accumulate).
#define BKK     32
#define ROWA    80
#define ATILE_B (256*ROWA)         // 20480
#define BTILE_B (128*128)          // 16384
#define STAGEB  (ATILE_B+BTILE_B)  // 36864
#define STAGES  4
#define KTILES  (CC/BKK)           // 64
#define GEMM_SMEM (STAGES*STAGEB)  // 147456

// Multi-matrix: grid.x = nmat*16, sel = blockIdx.x>>4 picks (B, C, bias).
template <int EPI>
__global__ void __launch_bounds__(256, 1)
gemm_multi(const __half* __restrict__ Ah,
           const __half* __restrict__ B0h, const __half* __restrict__ B0l,
           const __half* __restrict__ B1h, const __half* __restrict__ B1l,
           const __half* __restrict__ B2h, const __half* __restrict__ B2l,
           float* __restrict__ C0, float* __restrict__ C1, float* __restrict__ C2,
           const float* __restrict__ bias0, const float* __restrict__ bias1)
{
    extern __shared__ char smem[];
    const uint32_t sb = smem_u32(smem);
    const int sel = blockIdx.x >> 4;
    const __half* Bh = sel == 0 ? B0h : sel == 1 ? B1h : B2h;
    const __half* Bl = sel == 0 ? B0l : sel == 1 ? B1l : B2l;
    float* C = sel == 0 ? C0 : sel == 1 ? C1 : C2;
    const float* bias = (sel == 0) ? bias0 : bias1;

    const int tid = threadIdx.x;
    const int lane = tid & 31;
    const int wid = tid >> 5;
    const int bm = blockIdx.y * 256;
    const int bn = (blockIdx.x & 15) * 128;
    const int wm = (wid >> 1) * 64;
    const int wn = (wid & 1) * 64;

    float acc[4][8][4];
#pragma unroll
    for (int i = 0; i < 4; i++)
#pragma unroll
        for (int j = 0; j < 8; j++)
#pragma unroll
            for (int r = 0; r < 4; r++) acc[i][j][r] = 0.f;

    // ldmatrix per-thread address components
    const uint32_t xm = (uint32_t)((lane & 7) << 4);            // B swizzle xor
    const int arow = lane & 15;
    const uint32_t ahalf = (uint32_t)((lane >> 4) << 4);        // 0 or 16
    const int brow = (lane & 7) | ((lane >> 4) << 3);
    const uint32_t bhalf = (uint32_t)(((lane >> 3) & 1) << 4);  // 0 or 16

    // stage loader: A 1024 + B 1024 16B units, 8 per thread
    auto load_stage = [&](int s, int kt) {
        uint32_t base = sb + s * STAGEB;
        int k0 = kt * BKK;
#pragma unroll
        for (int i = 0; i < 4; i++) {
            int u = tid + i * 256;
            int r = u >> 2, c = u & 3;
            cp16(base + r * ROWA + c * 16, Ah + (size_t)(bm + r) * CC + k0 + c * 8);
        }
#pragma unroll
        for (int i = 0; i < 4; i++) {
            int u = tid + i * 256;
            int r = u >> 3, c = u & 7;
            const __half* src = ((c & 4) ? Bl : Bh) + (size_t)(bn + r) * CC + k0 + (c & 3) * 8;
            cp16(base + ATILE_B + r * 128 + ((uint32_t)(c * 16) ^ (uint32_t)((r & 7) << 4)), src);
        }
    };

    load_stage(0, 0); CP_COMMIT();
    load_stage(1, 1); CP_COMMIT();
    load_stage(2, 2); CP_COMMIT();

    for (int kt = 0; kt < KTILES; kt++) {
        if (kt <= KTILES - 3)      cp_wait<2>();
        else if (kt == KTILES - 2) cp_wait<1>();
        else                       cp_wait<0>();
        __syncthreads();
        if (kt + 3 < KTILES) { load_stage((kt + 3) % STAGES, kt + 3); CP_COMMIT(); }

        const uint32_t st = sb + (kt % STAGES) * STAGEB;
        const uint32_t aBase = st + (uint32_t)((wm + arow) * ROWA);
        const uint32_t bBase = st + ATILE_B + (uint32_t)((wn + brow) * 128);
#pragma unroll
        for (int ks = 0; ks < 2; ks++) {
            uint32_t ah[4][4];
            const uint32_t aoff = (uint32_t)(ks * 32) + ahalf;
#pragma unroll
            for (int mi = 0; mi < 4; mi++)
                ldsm4(ah[mi], aBase + mi * 16 * ROWA + aoff);
            const uint32_t boff_h = ((uint32_t)(ks * 32) + bhalf) ^ xm;
            const uint32_t boff_l = ((uint32_t)(ks * 32) + bhalf + 64) ^ xm;
#pragma unroll
            for (int jj = 0; jj < 4; jj++) {
                uint32_t bh[4], bl[4];
                ldsm4(bh, bBase + jj * 2048 + boff_h);
                ldsm4(bl, bBase + jj * 2048 + boff_l);
#pragma unroll
                for (int mi = 0; mi < 4; mi++) {
                    mma_f16(acc[mi][2*jj],   ah[mi], bh);
                    mma_f16(acc[mi][2*jj+1], ah[mi], bh + 2);
                    mma_f16(acc[mi][2*jj],   ah[mi], bl);
                    mma_f16(acc[mi][2*jj+1], ah[mi], bl + 2);
                }
            }
        }
    }

    // epilogue
    const int gr = lane >> 2, ti = lane & 3;
#pragma unroll
    for (int mi = 0; mi < 4; mi++) {
        int m0 = bm + wm + mi * 16 + gr;
#pragma unroll
        for (int j = 0; j < 8; j++) {
            int col = bn + wn + j * 8 + ti * 2;
            float2 v0 = make_float2(acc[mi][j][0], acc[mi][j][1]);
            float2 v1 = make_float2(acc[mi][j][2], acc[mi][j][3]);
            if (EPI == 1) {
                float b0 = bias[col], b1 = bias[col + 1];
                v0.x = sigmoidf(v0.x + b0); v0.y = sigmoidf(v0.y + b1);
                v1.x = sigmoidf(v1.x + b0); v1.y = sigmoidf(v1.y + b1);
            }
            *(float2*)(C + (size_t)m0 * CC + col) = v0;
            *(float2*)(C + (size_t)(m0 + 8) * CC + col) = v1;
        }
    }
}

// ---------------- causal depthwise conv (K=4) + SiLU + fp16 cast -----------
__global__ void conv_silu_kernel(const float* __restrict__ x,
                                 const float* __restrict__ w,
                                 const float* __restrict__ b) {
    int idx = blockIdx.x * blockDim.x + threadIdx.x;
    if (idx >= NTOT) return;
    int c = idx & (CC - 1);
    int t = (idx / CC) & (TT - 1);
    float acc = b[c];
    const float* wc = w + c * KK;
#pragma unroll
    for (int j = 0; j < KK; j++) {
        int tt = t - (KK - 1) + j;
        if (tt >= 0) acc = fmaf(x[idx + (j - (KK - 1)) * CC], wc[j], acc);
    }
    float y = acc * sigmoidf(acc);
    g_xc[idx] = y;
    g_ch[idx] = __float2half(y);
}

// ---------------- gamma = sigmoid(xc @ gamma_w^T + gamma_b), fp32 ----------
__global__ void gamma_kernel(const float* __restrict__ gw, const float* __restrict__ gb) {
    __shared__ float sx[CC];
    int n = blockIdx.x;
    const float* xr = g_xc + (size_t)n * CC;
    for (int i = threadIdx.x; i < CC; i += 128) sx[i] = xr[i];
    __syncthreads();
    int warp = threadIdx.x >> 5, lane = threadIdx.x & 31;
    for (int h = warp; h < HH; h += 4) {
        const float* w = gw + (size_t)h * CC;
        float s = 0.f;
        for (int k = lane; k < CC; k += 32) s = fmaf(sx[k], w[k], s);
        s = warp_sum(s);
        if (lane == 0) g_gamma[(size_t)n * HH + h] = sigmoidf(s + gb[h]);
    }
}

// ---------------- per-(token,head) L2 norm over D=128 (in place) -----------
__global__ void l2norm_kernel(float* __restrict__ p) {
    int gw = (blockIdx.x * blockDim.x + threadIdx.x) >> 5;
    int lane = threadIdx.x & 31;
    if (gw >= NTOK * HH) return;
    float4* row = (float4*)(p + (size_t)gw * DD);
    float4 a = row[lane];
    float ss = a.x * a.x + a.y * a.y + a.z * a.z + a.w * a.w;
    ss = warp_sum(ss);
    float inv = 1.f / fmaxf(sqrtf(ss), 1e-12f);
    a.x *= inv; a.y *= inv; a.z *= inv; a.w *= inv;
    row[lane] = a;
}

// ---------------- fused: v LayerNorm + kv = ig * k * vn (in place on g_v) --
__global__ void vln_kv_kernel(const float* __restrict__ g, const float* __restrict__ b) {
    int gw = (blockIdx.x * blockDim.x + threadIdx.x) >> 5;
    int lane = threadIdx.x & 31;
    if (gw >= NTOK * HH) return;
    size_t off = (size_t)gw * DD + lane * 4;
    float4 a = *(float4*)(g_v + off);
    float s = a.x + a.y + a.z + a.w;
    float ss = a.x * a.x + a.y * a.y + a.z * a.z + a.w * a.w;
    s = warp_sum(s); ss = warp_sum(ss);
    float mean = s * (1.f / DD);
    float var = ss * (1.f / DD) - mean * mean;
    float r = rsqrtf(var + 1e-5f);
    int d = lane * 4;
    float4 ig = *(const float4*)(g_ig + off);
    float4 k  = *(const float4*)(g_k + off);
    a.x = ((a.x - mean) * r * g[d + 0] + b[d + 0]) * ig.x * k.x;
    a.y = ((a.y - mean) * r * g[d + 1] + b[d + 1]) * ig.y * k.y;
    a.z = ((a.z - mean) * r * g[d + 2] + b[d + 2]) * ig.z * k.z;
    a.w = ((a.w - mean) * r * g[d + 3] + b[d + 3]) * ig.w * k.w;
    *(float4*)(g_v + off) = a;
}

// ---------------- chunked scan: pass A (local scans) -----------------------
// block = (b*HH+h)*NCH + chunk, 128 threads (d). Local scan over CHL steps,
// writes local mem in place, chunk carry, and cumulative gamma per t.
__global__ void scan_local_kernel() {
    int blk = blockIdx.x;
    int chunk = blk & (NCH - 1);
    int bh = blk / NCH;
    int b = bh / HH, h = bh % HH;
    int d = threadIdx.x;
    int t0 = chunk * CHL;
    size_t idx = ((size_t)(b * TT + t0) * HH + h) * DD + d;
    const float* gam = g_gamma + (size_t)(b * TT + t0) * HH + h;
    float* cumg = g_cumG + (size_t)bh * TT + t0;
    float mem = 0.f, cg = 1.f;
#pragma unroll 4
    for (int tt = 0; tt < CHL; tt++) {
        float g = __ldg(gam + (size_t)tt * HH);
        mem = fmaf(g, mem, g_v[idx]);
        g_v[idx] = mem;
        cg *= g;
        if (d == 0) cumg[tt] = cg;
        idx += (size_t)HH * DD;
    }
    g_carry[(size_t)blk * DD + d] = mem;
}

// ---------------- chunked scan: pass B (combine carries) -------------------
__global__ void scan_carry_kernel() {
    int bh = blockIdx.x;
    int d = threadIdx.x;
    float p = 0.f;
    for (int c = 0; c < NCH; c++) {
        g_prefix[((size_t)bh * NCH + c) * DD + d] = p;
        float G = g_cumG[(size_t)bh * TT + c * CHL + CHL - 1];
        p = g_carry[((size_t)bh * NCH + c) * DD + d] + G * p;
    }
}

// -------- prefix apply + LN(mem)*q -> GroupNorm -> *og -> fp16 cast --------
__global__ void post_kernel(const float* __restrict__ mn_g, const float* __restrict__ mn_b,
                            const float* __restrict__ gn_g, const float* __restrict__ gn_b) {
    int row = (blockIdx.x * blockDim.x + threadIdx.x) >> 5;
    int lane = threadIdx.x & 31;
    if (row >= NTOK * HH) return;
    size_t off = (size_t)row * DD + lane * 4;
    float4 m  = *(const float4*)(g_v + off);
    float4 q  = *(const float4*)(g_q + off);
    float4 og = *(const float4*)(g_og + off);

    // reconstruct global scan: mem += prefix * cumG
    int b = row / (TT * HH);
    int t = (row / HH) & (TT - 1);
    int h = row & (HH - 1);
    int bh = b * HH + h;
    int chunk = t / CHL;
    float cg = g_cumG[(size_t)bh * TT + t];
    float4 pf = *(const float4*)(g_prefix + ((size_t)bh * NCH + chunk) * DD + lane * 4);
    m.x = fmaf(pf.x, cg, m.x);
    m.y = fmaf(pf.y, cg, m.y);
    m.z = fmaf(pf.z, cg, m.z);
    m.w = fmaf(pf.w, cg, m.w);

    float s = m.x + m.y + m.z + m.w;
    float ss = m.x * m.x + m.y * m.y + m.z * m.z + m.w * m.w;
    s = warp_sum(s); ss = warp_sum(ss);
    float mean = s * (1.f / DD);
    float var = ss * (1.f / DD) - mean * mean;
    float r = rsqrtf(var + 1e-5f);
    int d = lane * 4;
    float4 o1;
    o1.x = ((m.x - mean) * r * mn_g[d + 0] + mn_b[d + 0]) * q.x;
    o1.y = ((m.y - mean) * r * mn_g[d + 1] + mn_b[d + 1]) * q.y;
    o1.z = ((m.z - mean) * r * mn_g[d + 2] + mn_b[d + 2]) * q.z;
    o1.w = ((m.w - mean) * r * mn_g[d + 3] + mn_b[d + 3]) * q.w;

    float s2 = o1.x + o1.y + o1.z + o1.w;
    float ss2 = o1.x * o1.x + o1.y * o1.y + o1.z * o1.z + o1.w * o1.w;
    s2 = warp_sum(s2); ss2 = warp_sum(ss2);
    float mean2 = s2 * (1.f / DD);
    float var2 = ss2 * (1.f / DD) - mean2 * mean2;
    float r2 = rsqrtf(var2 + 1e-5f);
    int c = h * DD + d;
    float ov0 = (((o1.x - mean2) * r2) * gn_g[c + 0] + gn_b[c + 0]) * og.x;
    float ov1 = (((o1.y - mean2) * r2) * gn_g[c + 1] + gn_b[c + 1]) * og.y;
    float ov2 = (((o1.z - mean2) * r2) * gn_g[c + 2] + gn_b[c + 2]) * og.z;
    float ov3 = (((o1.w - mean2) * r2) * gn_g[c + 3] + gn_b[c + 3]) * og.w;
    __half2* dst = (__half2*)(g_oh + off);
    dst[0] = __floats2half2_rn(ov0, ov1);
    dst[1] = __floats2half2_rn(ov2, ov3);
}

// ---------------- launch ----------------------------------------------------
extern "C" void kernel_launch(void* const* d_in, const int* in_sizes, int n_in,
                              void* d_out, int out_size) {
    const float* x       = (const float*)d_in[0];
    const float* Wq      = (const float*)d_in[1];
    const float* Wk      = (const float*)d_in[2];
    const float* Wv      = (const float*)d_in[3];
    const float* Wo      = (const float*)d_in[4];
    const float* conv_w  = (const float*)d_in[5];
    const float* conv_b  = (const float*)d_in[6];
    const float* ig_w    = (const float*)d_in[7];
    const float* ig_b    = (const float*)d_in[8];
    const float* og_w    = (const float*)d_in[9];
    const float* og_b    = (const float*)d_in[10];
    const float* gamma_w = (const float*)d_in[11];
    const float* gamma_b = (const float*)d_in[12];
    const float* vn_g    = (const float*)d_in[13];
    const float* vn_b    = (const float*)d_in[14];
    const float* gn_g    = (const float*)d_in[15];
    const float* gn_b    = (const float*)d_in[16];
    const float* mn_g    = (const float*)d_in[17];
    const float* mn_b    = (const float*)d_in[18];
    float* out = (float*)d_out;

    float *p_q, *p_k, *p_v, *p_ig, *p_og;
    cudaGetSymbolAddress((void**)&p_q,  g_q);
    cudaGetSymbolAddress((void**)&p_k,  g_k);
    cudaGetSymbolAddress((void**)&p_v,  g_v);
    cudaGetSymbolAddress((void**)&p_ig, g_ig);
    cudaGetSymbolAddress((void**)&p_og, g_og);

    __half *p_xh, *p_ch, *p_oh, *p_wh, *p_wl;
    cudaGetSymbolAddress((void**)&p_xh, g_xh);
    cudaGetSymbolAddress((void**)&p_ch, g_ch);
    cudaGetSymbolAddress((void**)&p_oh, g_oh);
    cudaGetSymbolAddress((void**)&p_wh, g_wh);
    cudaGetSymbolAddress((void**)&p_wl, g_wl);

    cudaFuncSetAttribute(gemm_multi<0>, cudaFuncAttributeMaxDynamicSharedMemorySize, GEMM_SMEM);
    cudaFuncSetAttribute(gemm_multi<1>, cudaFuncAttributeMaxDynamicSharedMemorySize, GEMM_SMEM);

    const size_t WSZ = (size_t)CC * CC;   // 4M elems per weight matrix

    conv_silu_kernel<<<NTOT / 256, 256>>>(x, conv_w, conv_b);
    cvt_h_kernel<<<NTOT / 256, 256>>>(x, p_xh, NTOT);
    cvt_w_kernel<<<(6 * (int)WSZ) / 256, 256>>>(Wq, Wk, Wv, ig_w, og_w, Wo);

    // q, k, v fused into one launch (sel = blockIdx.x>>4)
    {
        dim3 grid(48, NTOK / 256);
        gemm_multi<0><<<grid, 256, GEMM_SMEM>>>(p_xh,
            p_wh + 0*WSZ, p_wl + 0*WSZ, p_wh + 1*WSZ, p_wl + 1*WSZ, p_wh + 2*WSZ, p_wl + 2*WSZ,
            p_q, p_k, p_v, nullptr, nullptr);
    }
    // ig, og fused (with sigmoid+bias epilogue)
    {
        dim3 grid(32, NTOK / 256);
        gemm_multi<1><<<grid, 256, GEMM_SMEM>>>(p_ch,
            p_wh + 3*WSZ, p_wl + 3*WSZ, p_wh + 4*WSZ, p_wl + 4*WSZ, p_wh + 4*WSZ, p_wl + 4*WSZ,
            p_ig, p_og, p_og, ig_b, og_b);
    }

    gamma_kernel<<<NTOK, 128>>>(gamma_w, gamma_b);

    int nrows = NTOK * HH;                       // 131072 rows of 128
    int rblocks = nrows / 8;
    l2norm_kernel<<<rblocks, 256>>>(p_q);
    l2norm_kernel<<<rblocks, 256>>>(p_k);
    vln_kv_kernel<<<rblocks, 256>>>(vn_g, vn_b);

    scan_local_kernel<<<BB * HH * NCH, DD>>>();
    scan_carry_kernel<<<BB * HH, DD>>>();

    post_kernel<<<rblocks, 256>>>(mn_g, mn_b, gn_g, gn_b);

    // final projection
    {
        dim3 grid(16, NTOK / 256);
        gemm_multi<0><<<grid, 256, GEMM_SMEM>>>(p_oh,
            p_wh + 5*WSZ, p_wl + 5*WSZ, p_wh + 5*WSZ, p_wl + 5*WSZ, p_wh + 5*WSZ, p_wl + 5*WSZ,
            out, out, out, nullptr, nullptr);
    }
}

// round 9
// speedup vs baseline: 4.0966x; 1.1543x over previous
#include <cuda_runtime.h>
#include <cuda_fp16.h>
#include <math.h>
#include <stdint.h>

// Problem constants
#define BB 2
#define TT 4096
#define CC 2048
#define HH 16
#define DD 128
#define KK 4
#define NTOK (BB*TT)          // 8192 tokens
#define NTOT (BB*TT*CC)       // 16777216 elements
#define NCH  32               // scan chunks
#define CHL  (TT/NCH)         // 128 timesteps per chunk

// ---------------- scratch (device globals: allocation-free) ----------------
__device__ float g_xc[NTOT];      // conv+silu output (fp32, feeds gamma GEMM)
__device__ float g_q [NTOT];
__device__ float g_k [NTOT];
__device__ float g_v [NTOT];      // v -> kv -> local mem (in place)
__device__ float g_ig[NTOT];
__device__ float g_og[NTOT];
__device__ float g_gamma[NTOK*HH];
__device__ float g_cumG[BB*HH*TT];          // per-chunk cumulative gamma
__device__ float g_carry[BB*HH*NCH*DD];     // chunk-final local mem
__device__ float g_prefix[BB*HH*NCH*DD];    // incoming prefix per chunk

// fp16 buffers (A-side: hi only; weights: hi+lo)
__device__ __half g_xh[NTOT];               // x (hi)
__device__ __half g_ch[NTOT];               // xc (hi)
__device__ __half g_oh[NTOT];               // gated output (hi)
__device__ __half g_wh[6*CC*CC], g_wl[6*CC*CC]; // Wq,Wk,Wv,ig_w,og_w,Wo

// ---------------- helpers ----------------
__device__ __forceinline__ float warp_sum(float v) {
#pragma unroll
    for (int o = 16; o; o >>= 1) v += __shfl_xor_sync(0xFFFFFFFFu, v, o);
    return v;
}
__device__ __forceinline__ float sigmoidf(float x) { return 1.f / (1.f + expf(-x)); }

__device__ __forceinline__ uint32_t smem_u32(const void* p) {
    uint32_t a;
    asm("{ .reg .u64 t; cvta.to.shared.u64 t, %1; cvt.u32.u64 %0, t; }" : "=r"(a) : "l"(p));
    return a;
}
__device__ __forceinline__ void cp16(uint32_t dst, const void* src) {
    asm volatile("cp.async.cg.shared.global [%0], [%1], 16;" :: "r"(dst), "l"(src));
}
#define CP_COMMIT() asm volatile("cp.async.commit_group;" ::: "memory")
template <int N>
__device__ __forceinline__ void cp_wait() { asm volatile("cp.async.wait_group %0;" :: "n"(N) : "memory"); }

__device__ __forceinline__ void ldsm4(uint32_t* r, uint32_t addr) {
    asm volatile("ldmatrix.sync.aligned.m8n8.x4.shared.b16 {%0,%1,%2,%3}, [%4];"
                 : "=r"(r[0]), "=r"(r[1]), "=r"(r[2]), "=r"(r[3]) : "r"(addr));
}
__device__ __forceinline__ void mma_f16(float* c, const uint32_t* a, const uint32_t* b) {
    asm volatile(
        "mma.sync.aligned.m16n8k16.row.col.f32.f16.f16.f32 "
        "{%0,%1,%2,%3}, {%4,%5,%6,%7}, {%8,%9}, {%0,%1,%2,%3};"
        : "+f"(c[0]), "+f"(c[1]), "+f"(c[2]), "+f"(c[3])
        : "r"(a[0]), "r"(a[1]), "r"(a[2]), "r"(a[3]), "r"(b[0]), "r"(b[1]));
}

// ---------------- conversions ----------------
__global__ void cvt_h_kernel(const float* __restrict__ s, __half* __restrict__ h, int n) {
    int i = blockIdx.x * blockDim.x + threadIdx.x;
    if (i >= n) return;
    h[i] = __float2half(s[i]);
}

// split all 6 weight matrices in one launch
__global__ void cvt_w_kernel(const float* __restrict__ w0, const float* __restrict__ w1,
                             const float* __restrict__ w2, const float* __restrict__ w3,
                             const float* __restrict__ w4, const float* __restrict__ w5) {
    int i = blockIdx.x * blockDim.x + threadIdx.x;           // 0 .. 6*WSZ-1
    const int WSZ = CC * CC;
    int j = i / WSZ, r = i - j * WSZ;
    const float* src = j == 0 ? w0 : j == 1 ? w1 : j == 2 ? w2 : j == 3 ? w3 : j == 4 ? w4 : w5;
    float v = src[r];
    __half hi = __float2half(v);
    g_wh[i] = hi;
    g_wl[i] = __float2half(v - __half2float(hi));
}

// ---------------- fp16 HMMA GEMM (2-product): C = A @ W^T -------------------
// CTA tile 128x128, BK=32, 4 warps (2x2), warp tile 64x64, 4-stage cp.async,
// 128 threads, 2 CTAs/SM (smem 104KB, regs ~215) for latency hiding.
// A: hi-only fp16, rows of 64B data + 16B pad (ROWA=80), no swizzle.
// B: [hi 64B | lo 64B] packed 128B rows, XOR swizzle (chunk ^= row&7).
// Products per k16: Ah*Bh + Ah*Bl (fp32 accumulate).
#define BKK     32
#define ROWA    80
#define ATILE_B (128*ROWA)         // 10240
#define BTILE_B (128*128)          // 16384
#define STAGEB  (ATILE_B+BTILE_B)  // 26624
#define STAGES  4
#define KTILES  (CC/BKK)           // 64
#define GEMM_SMEM (STAGES*STAGEB)  // 106496

// Multi-matrix: grid.x = nmat*16, sel = blockIdx.x>>4 picks (B, C, bias).
template <int EPI>
__global__ void __launch_bounds__(128, 2)
gemm_multi(const __half* __restrict__ Ah,
           const __half* __restrict__ B0h, const __half* __restrict__ B0l,
           const __half* __restrict__ B1h, const __half* __restrict__ B1l,
           const __half* __restrict__ B2h, const __half* __restrict__ B2l,
           float* __restrict__ C0, float* __restrict__ C1, float* __restrict__ C2,
           const float* __restrict__ bias0, const float* __restrict__ bias1)
{
    extern __shared__ char smem[];
    const uint32_t sb = smem_u32(smem);
    const int sel = blockIdx.x >> 4;
    const __half* Bh = sel == 0 ? B0h : sel == 1 ? B1h : B2h;
    const __half* Bl = sel == 0 ? B0l : sel == 1 ? B1l : B2l;
    float* C = sel == 0 ? C0 : sel == 1 ? C1 : C2;
    const float* bias = (sel == 0) ? bias0 : bias1;

    const int tid = threadIdx.x;
    const int lane = tid & 31;
    const int wid = tid >> 5;
    const int bm = blockIdx.y * 128;
    const int bn = (blockIdx.x & 15) * 128;
    const int wm = (wid >> 1) * 64;   // 0 or 64
    const int wn = (wid & 1) * 64;    // 0 or 64

    float acc[4][8][4];
#pragma unroll
    for (int i = 0; i < 4; i++)
#pragma unroll
        for (int j = 0; j < 8; j++)
#pragma unroll
            for (int r = 0; r < 4; r++) acc[i][j][r] = 0.f;

    // ldmatrix per-thread address components
    const uint32_t xm = (uint32_t)((lane & 7) << 4);            // B swizzle xor
    const int arow = lane & 15;
    const uint32_t ahalf = (uint32_t)((lane >> 4) << 4);        // 0 or 16
    const int brow = (lane & 7) | ((lane >> 4) << 3);
    const uint32_t bhalf = (uint32_t)(((lane >> 3) & 1) << 4);  // 0 or 16

    // stage loader: A 512 + B 1024 16B units, 12 per thread (128 threads)
    auto load_stage = [&](int s, int kt) {
        uint32_t base = sb + s * STAGEB;
        int k0 = kt * BKK;
#pragma unroll
        for (int i = 0; i < 4; i++) {
            int u = tid + i * 128;          // 0..511
            int r = u >> 2, c = u & 3;
            cp16(base + r * ROWA + c * 16, Ah + (size_t)(bm + r) * CC + k0 + c * 8);
        }
#pragma unroll
        for (int i = 0; i < 8; i++) {
            int u = tid + i * 128;          // 0..1023
            int r = u >> 3, c = u & 7;
            const __half* src = ((c & 4) ? Bl : Bh) + (size_t)(bn + r) * CC + k0 + (c & 3) * 8;
            cp16(base + ATILE_B + r * 128 + ((uint32_t)(c * 16) ^ (uint32_t)((r & 7) << 4)), src);
        }
    };

    load_stage(0, 0); CP_COMMIT();
    load_stage(1, 1); CP_COMMIT();
    load_stage(2, 2); CP_COMMIT();

    for (int kt = 0; kt < KTILES; kt++) {
        if (kt <= KTILES - 3)      cp_wait<2>();
        else if (kt == KTILES - 2) cp_wait<1>();
        else                       cp_wait<0>();
        __syncthreads();
        if (kt + 3 < KTILES) { load_stage((kt + 3) % STAGES, kt + 3); CP_COMMIT(); }

        const uint32_t st = sb + (kt % STAGES) * STAGEB;
        const uint32_t aBase = st + (uint32_t)((wm + arow) * ROWA);
        const uint32_t bBase = st + ATILE_B + (uint32_t)((wn + brow) * 128);
#pragma unroll
        for (int ks = 0; ks < 2; ks++) {
            uint32_t ah[4][4];
            const uint32_t aoff = (uint32_t)(ks * 32) + ahalf;
#pragma unroll
            for (int mi = 0; mi < 4; mi++)
                ldsm4(ah[mi], aBase + mi * 16 * ROWA + aoff);
            const uint32_t boff_h = ((uint32_t)(ks * 32) + bhalf) ^ xm;
            const uint32_t boff_l = ((uint32_t)(ks * 32) + bhalf + 64) ^ xm;
#pragma unroll
            for (int jj = 0; jj < 4; jj++) {
                uint32_t bh[4], bl[4];
                ldsm4(bh, bBase + jj * 2048 + boff_h);
                ldsm4(bl, bBase + jj * 2048 + boff_l);
#pragma unroll
                for (int mi = 0; mi < 4; mi++) {
                    mma_f16(acc[mi][2*jj],   ah[mi], bh);
                    mma_f16(acc[mi][2*jj+1], ah[mi], bh + 2);
                    mma_f16(acc[mi][2*jj],   ah[mi], bl);
                    mma_f16(acc[mi][2*jj+1], ah[mi], bl + 2);
                }
            }
        }
    }

    // epilogue
    const int gr = lane >> 2, ti = lane & 3;
#pragma unroll
    for (int mi = 0; mi < 4; mi++) {
        int m0 = bm + wm + mi * 16 + gr;
#pragma unroll
        for (int j = 0; j < 8; j++) {
            int col = bn + wn + j * 8 + ti * 2;
            float2 v0 = make_float2(acc[mi][j][0], acc[mi][j][1]);
            float2 v1 = make_float2(acc[mi][j][2], acc[mi][j][3]);
            if (EPI == 1) {
                float b0 = bias[col], b1 = bias[col + 1];
                v0.x = sigmoidf(v0.x + b0); v0.y = sigmoidf(v0.y + b1);
                v1.x = sigmoidf(v1.x + b0); v1.y = sigmoidf(v1.y + b1);
            }
            *(float2*)(C + (size_t)m0 * CC + col) = v0;
            *(float2*)(C + (size_t)(m0 + 8) * CC + col) = v1;
        }
    }
}

// ---------------- causal depthwise conv (K=4) + SiLU + fp16 cast -----------
__global__ void conv_silu_kernel(const float* __restrict__ x,
                                 const float* __restrict__ w,
                                 const float* __restrict__ b) {
    int idx = blockIdx.x * blockDim.x + threadIdx.x;
    if (idx >= NTOT) return;
    int c = idx & (CC - 1);
    int t = (idx / CC) & (TT - 1);
    float acc = b[c];
    const float* wc = w + c * KK;
#pragma unroll
    for (int j = 0; j < KK; j++) {
        int tt = t - (KK - 1) + j;
        if (tt >= 0) acc = fmaf(x[idx + (j - (KK - 1)) * CC], wc[j], acc);
    }
    float y = acc * sigmoidf(acc);
    g_xc[idx] = y;
    g_ch[idx] = __float2half(y);
}

// ------- gamma = sigmoid(xc @ gamma_w^T + gamma_b): 4 tokens per block -----
__global__ void gamma_kernel(const float* __restrict__ gw, const float* __restrict__ gb) {
    __shared__ float sx[4 * CC];   // 32KB
    int t0 = blockIdx.x * 4;
    for (int i = threadIdx.x; i < 4 * CC; i += 256)
        sx[i] = g_xc[(size_t)t0 * CC + i];
    __syncthreads();
    int warp = threadIdx.x >> 5, lane = threadIdx.x & 31;
    const float* xr = sx + (warp >> 1) * CC;     // token = warp>>1
    int hbase = (warp & 1) * 8;
#pragma unroll
    for (int hh = 0; hh < 8; hh++) {
        int h = hbase + hh;
        const float* w = gw + (size_t)h * CC;
        float s = 0.f;
        for (int k = lane; k < CC; k += 32) s = fmaf(xr[k], w[k], s);
        s = warp_sum(s);
        if (lane == 0) g_gamma[(size_t)(t0 + (warp >> 1)) * HH + h] = sigmoidf(s + gb[h]);
    }
}

// ---------------- per-(token,head) L2 norm over D=128 (in place) -----------
__global__ void l2norm_kernel(float* __restrict__ p) {
    int gw = (blockIdx.x * blockDim.x + threadIdx.x) >> 5;
    int lane = threadIdx.x & 31;
    if (gw >= NTOK * HH) return;
    float4* row = (float4*)(p + (size_t)gw * DD);
    float4 a = row[lane];
    float ss = a.x * a.x + a.y * a.y + a.z * a.z + a.w * a.w;
    ss = warp_sum(ss);
    float inv = 1.f / fmaxf(sqrtf(ss), 1e-12f);
    a.x *= inv; a.y *= inv; a.z *= inv; a.w *= inv;
    row[lane] = a;
}

// ---------------- fused: v LayerNorm + kv = ig * k * vn (in place on g_v) --
__global__ void vln_kv_kernel(const float* __restrict__ g, const float* __restrict__ b) {
    int gw = (blockIdx.x * blockDim.x + threadIdx.x) >> 5;
    int lane = threadIdx.x & 31;
    if (gw >= NTOK * HH) return;
    size_t off = (size_t)gw * DD + lane * 4;
    float4 a = *(float4*)(g_v + off);
    float s = a.x + a.y + a.z + a.w;
    float ss = a.x * a.x + a.y * a.y + a.z * a.z + a.w * a.w;
    s = warp_sum(s); ss = warp_sum(ss);
    float mean = s * (1.f / DD);
    float var = ss * (1.f / DD) - mean * mean;
    float r = rsqrtf(var + 1e-5f);
    int d = lane * 4;
    float4 ig = *(const float4*)(g_ig + off);
    float4 k  = *(const float4*)(g_k + off);
    a.x = ((a.x - mean) * r * g[d + 0] + b[d + 0]) * ig.x * k.x;
    a.y = ((a.y - mean) * r * g[d + 1] + b[d + 1]) * ig.y * k.y;
    a.z = ((a.z - mean) * r * g[d + 2] + b[d + 2]) * ig.z * k.z;
    a.w = ((a.w - mean) * r * g[d + 3] + b[d + 3]) * ig.w * k.w;
    *(float4*)(g_v + off) = a;
}

// ---------------- chunked scan: pass A (local scans) -----------------------
__global__ void scan_local_kernel() {
    int blk = blockIdx.x;
    int chunk = blk & (NCH - 1);
    int bh = blk / NCH;
    int b = bh / HH, h = bh % HH;
    int d = threadIdx.x;
    int t0 = chunk * CHL;
    size_t idx = ((size_t)(b * TT + t0) * HH + h) * DD + d;
    const float* gam = g_gamma + (size_t)(b * TT + t0) * HH + h;
    float* cumg = g_cumG + (size_t)bh * TT + t0;
    float mem = 0.f, cg = 1.f;
#pragma unroll 4
    for (int tt = 0; tt < CHL; tt++) {
        float g = __ldg(gam + (size_t)tt * HH);
        mem = fmaf(g, mem, g_v[idx]);
        g_v[idx] = mem;
        cg *= g;
        if (d == 0) cumg[tt] = cg;
        idx += (size_t)HH * DD;
    }
    g_carry[(size_t)blk * DD + d] = mem;
}

// ---------------- chunked scan: pass B (combine carries) -------------------
__global__ void scan_carry_kernel() {
    int bh = blockIdx.x;
    int d = threadIdx.x;
    float p = 0.f;
    for (int c = 0; c < NCH; c++) {
        g_prefix[((size_t)bh * NCH + c) * DD + d] = p;
        float G = g_cumG[(size_t)bh * TT + c * CHL + CHL - 1];
        p = g_carry[((size_t)bh * NCH + c) * DD + d] + G * p;
    }
}

// -------- prefix apply + LN(mem)*q -> GroupNorm -> *og -> fp16 cast --------
__global__ void post_kernel(const float* __restrict__ mn_g, const float* __restrict__ mn_b,
                            const float* __restrict__ gn_g, const float* __restrict__ gn_b) {
    int row = (blockIdx.x * blockDim.x + threadIdx.x) >> 5;
    int lane = threadIdx.x & 31;
    if (row >= NTOK * HH) return;
    size_t off = (size_t)row * DD + lane * 4;
    float4 m  = *(const float4*)(g_v + off);
    float4 q  = *(const float4*)(g_q + off);
    float4 og = *(const float4*)(g_og + off);

    // reconstruct global scan: mem += prefix * cumG
    int b = row / (TT * HH);
    int t = (row / HH) & (TT - 1);
    int h = row & (HH - 1);
    int bh = b * HH + h;
    int chunk = t / CHL;
    float cg = g_cumG[(size_t)bh * TT + t];
    float4 pf = *(const float4*)(g_prefix + ((size_t)bh * NCH + chunk) * DD + lane * 4);
    m.x = fmaf(pf.x, cg, m.x);
    m.y = fmaf(pf.y, cg, m.y);
    m.z = fmaf(pf.z, cg, m.z);
    m.w = fmaf(pf.w, cg, m.w);

    float s = m.x + m.y + m.z + m.w;
    float ss = m.x * m.x + m.y * m.y + m.z * m.z + m.w * m.w;
    s = warp_sum(s); ss = warp_sum(ss);
    float mean = s * (1.f / DD);
    float var = ss * (1.f / DD) - mean * mean;
    float r = rsqrtf(var + 1e-5f);
    int d = lane * 4;
    float4 o1;
    o1.x = ((m.x - mean) * r * mn_g[d + 0] + mn_b[d + 0]) * q.x;
    o1.y = ((m.y - mean) * r * mn_g[d + 1] + mn_b[d + 1]) * q.y;
    o1.z = ((m.z - mean) * r * mn_g[d + 2] + mn_b[d + 2]) * q.z;
    o1.w = ((m.w - mean) * r * mn_g[d + 3] + mn_b[d + 3]) * q.w;

    float s2 = o1.x + o1.y + o1.z + o1.w;
    float ss2 = o1.x * o1.x + o1.y * o1.y + o1.z * o1.z + o1.w * o1.w;
    s2 = warp_sum(s2); ss2 = warp_sum(ss2);
    float mean2 = s2 * (1.f / DD);
    float var2 = ss2 * (1.f / DD) - mean2 * mean2;
    float r2 = rsqrtf(var2 + 1e-5f);
    int c = h * DD + d;
    float ov0 = (((o1.x - mean2) * r2) * gn_g[c + 0] + gn_b[c + 0]) * og.x;
    float ov1 = (((o1.y - mean2) * r2) * gn_g[c + 1] + gn_b[c + 1]) * og.y;
    float ov2 = (((o1.z - mean2) * r2) * gn_g[c + 2] + gn_b[c + 2]) * og.z;
    float ov3 = (((o1.w - mean2) * r2) * gn_g[c + 3] + gn_b[c + 3]) * og.w;
    __half2* dst = (__half2*)(g_oh + off);
    dst[0] = __floats2half2_rn(ov0, ov1);
    dst[1] = __floats2half2_rn(ov2, ov3);
}

// ---------------- launch ----------------------------------------------------
extern "C" void kernel_launch(void* const* d_in, const int* in_sizes, int n_in,
                              void* d_out, int out_size) {
    const float* x       = (const float*)d_in[0];
    const float* Wq      = (const float*)d_in[1];
    const float* Wk      = (const float*)d_in[2];
    const float* Wv      = (const float*)d_in[3];
    const float* Wo      = (const float*)d_in[4];
    const float* conv_w  = (const float*)d_in[5];
    const float* conv_b  = (const float*)d_in[6];
    const float* ig_w    = (const float*)d_in[7];
    const float* ig_b    = (const float*)d_in[8];
    const float* og_w    = (const float*)d_in[9];
    const float* og_b    = (const float*)d_in[10];
    const float* gamma_w = (const float*)d_in[11];
    const float* gamma_b = (const float*)d_in[12];
    const float* vn_g    = (const float*)d_in[13];
    const float* vn_b    = (const float*)d_in[14];
    const float* gn_g    = (const float*)d_in[15];
    const float* gn_b    = (const float*)d_in[16];
    const float* mn_g    = (const float*)d_in[17];
    const float* mn_b    = (const float*)d_in[18];
    float* out = (float*)d_out;

    float *p_q, *p_k, *p_v, *p_ig, *p_og;
    cudaGetSymbolAddress((void**)&p_q,  g_q);
    cudaGetSymbolAddress((void**)&p_k,  g_k);
    cudaGetSymbolAddress((void**)&p_v,  g_v);
    cudaGetSymbolAddress((void**)&p_ig, g_ig);
    cudaGetSymbolAddress((void**)&p_og, g_og);

    __half *p_xh, *p_ch, *p_oh, *p_wh, *p_wl;
    cudaGetSymbolAddress((void**)&p_xh, g_xh);
    cudaGetSymbolAddress((void**)&p_ch, g_ch);
    cudaGetSymbolAddress((void**)&p_oh, g_oh);
    cudaGetSymbolAddress((void**)&p_wh, g_wh);
    cudaGetSymbolAddress((void**)&p_wl, g_wl);

    cudaFuncSetAttribute(gemm_multi<0>, cudaFuncAttributeMaxDynamicSharedMemorySize, GEMM_SMEM);
    cudaFuncSetAttribute(gemm_multi<1>, cudaFuncAttributeMaxDynamicSharedMemorySize, GEMM_SMEM);

    const size_t WSZ = (size_t)CC * CC;   // 4M elems per weight matrix

    conv_silu_kernel<<<NTOT / 256, 256>>>(x, conv_w, conv_b);
    cvt_h_kernel<<<NTOT / 256, 256>>>(x, p_xh, NTOT);
    cvt_w_kernel<<<(6 * (int)WSZ) / 256, 256>>>(Wq, Wk, Wv, ig_w, og_w, Wo);

    // q, k, v fused into one launch (sel = blockIdx.x>>4)
    {
        dim3 grid(48, NTOK / 128);
        gemm_multi<0><<<grid, 128, GEMM_SMEM>>>(p_xh,
            p_wh + 0*WSZ, p_wl + 0*WSZ, p_wh + 1*WSZ, p_wl + 1*WSZ, p_wh + 2*WSZ, p_wl + 2*WSZ,
            p_q, p_k, p_v, nullptr, nullptr);
    }
    // ig, og fused (with sigmoid+bias epilogue)
    {
        dim3 grid(32, NTOK / 128);
        gemm_multi<1><<<grid, 128, GEMM_SMEM>>>(p_ch,
            p_wh + 3*WSZ, p_wl + 3*WSZ, p_wh + 4*WSZ, p_wl + 4*WSZ, p_wh + 4*WSZ, p_wl + 4*WSZ,
            p_ig, p_og, p_og, ig_b, og_b);
    }

    gamma_kernel<<<NTOK / 4, 256>>>(gamma_w, gamma_b);

    int nrows = NTOK * HH;                       // 131072 rows of 128
    int rblocks = nrows / 8;
    l2norm_kernel<<<rblocks, 256>>>(p_q);
    l2norm_kernel<<<rblocks, 256>>>(p_k);
    vln_kv_kernel<<<rblocks, 256>>>(vn_g, vn_b);

    scan_local_kernel<<<BB * HH * NCH, DD>>>();
    scan_carry_kernel<<<BB * HH, DD>>>();

    post_kernel<<<rblocks, 256>>>(mn_g, mn_b, gn_g, gn_b);

    // final projection
    {
        dim3 grid(16, NTOK / 128);
        gemm_multi<0><<<grid, 128, GEMM_SMEM>>>(p_oh,
            p_wh + 5*WSZ, p_wl + 5*WSZ, p_wh + 5*WSZ, p_wl + 5*WSZ, p_wh + 5*WSZ, p_wl + 5*WSZ,
            out, out, out, nullptr, nullptr);
    }
}

// round 10
// speedup vs baseline: 4.1459x; 1.0120x over previous
#include <cuda_runtime.h>
#include <cuda_fp16.h>
#include <math.h>
#include <stdint.h>

// Problem constants
#define BB 2
#define TT 4096
#define CC 2048
#define HH 16
#define DD 128
#define KK 4
#define NTOK (BB*TT)          // 8192 tokens
#define NTOT (BB*TT*CC)       // 16777216 elements
#define NCH  32               // scan chunks
#define CHL  (TT/NCH)         // 128 timesteps per chunk

// ---------------- scratch (device globals: allocation-free) ----------------
__device__ float g_xc[NTOT];      // conv+silu output (fp32, feeds gamma GEMM)
__device__ float g_q [NTOT];      // q (L2-normalized in GEMM epilogue)
__device__ float g_k [NTOT];      // k (L2-normalized in GEMM epilogue)
__device__ float g_v [NTOT];      // v (LayerNormed) -> local mem (in place)
__device__ float g_ig[NTOT];
__device__ float g_og[NTOT];
__device__ float g_gamma[NTOK*HH];
__device__ float g_cumG[BB*HH*TT];          // per-chunk cumulative gamma
__device__ float g_carry[BB*HH*NCH*DD];     // chunk-final local mem
__device__ float g_prefix[BB*HH*NCH*DD];    // incoming prefix per chunk

// fp16 buffers (A-side: hi only; weights: hi+lo)
__device__ __half g_xh[NTOT];               // x (hi)
__device__ __half g_ch[NTOT];               // xc (hi)
__device__ __half g_oh[NTOT];               // gated output (hi)
__device__ __half g_wh[6*CC*CC], g_wl[6*CC*CC]; // Wq,Wk,Wv,ig_w,og_w,Wo

// ---------------- helpers ----------------
__device__ __forceinline__ float warp_sum(float v) {
#pragma unroll
    for (int o = 16; o; o >>= 1) v += __shfl_xor_sync(0xFFFFFFFFu, v, o);
    return v;
}
__device__ __forceinline__ float sigmoidf(float x) { return 1.f / (1.f + expf(-x)); }

__device__ __forceinline__ uint32_t smem_u32(const void* p) {
    uint32_t a;
    asm("{ .reg .u64 t; cvta.to.shared.u64 t, %1; cvt.u32.u64 %0, t; }" : "=r"(a) : "l"(p));
    return a;
}
__device__ __forceinline__ void cp16(uint32_t dst, const void* src) {
    asm volatile("cp.async.cg.shared.global [%0], [%1], 16;" :: "r"(dst), "l"(src));
}
#define CP_COMMIT() asm volatile("cp.async.commit_group;" ::: "memory")
template <int N>
__device__ __forceinline__ void cp_wait() { asm volatile("cp.async.wait_group %0;" :: "n"(N) : "memory"); }

__device__ __forceinline__ void ldsm4(uint32_t* r, uint32_t addr) {
    asm volatile("ldmatrix.sync.aligned.m8n8.x4.shared.b16 {%0,%1,%2,%3}, [%4];"
                 : "=r"(r[0]), "=r"(r[1]), "=r"(r[2]), "=r"(r[3]) : "r"(addr));
}
__device__ __forceinline__ void mma_f16(float* c, const uint32_t* a, const uint32_t* b) {
    asm volatile(
        "mma.sync.aligned.m16n8k16.row.col.f32.f16.f16.f32 "
        "{%0,%1,%2,%3}, {%4,%5,%6,%7}, {%8,%9}, {%0,%1,%2,%3};"
        : "+f"(c[0]), "+f"(c[1]), "+f"(c[2]), "+f"(c[3])
        : "r"(a[0]), "r"(a[1]), "r"(a[2]), "r"(a[3]), "r"(b[0]), "r"(b[1]));
}

// split all 6 weight matrices in one launch
__global__ void cvt_w_kernel(const float* __restrict__ w0, const float* __restrict__ w1,
                             const float* __restrict__ w2, const float* __restrict__ w3,
                             const float* __restrict__ w4, const float* __restrict__ w5) {
    int i = blockIdx.x * blockDim.x + threadIdx.x;           // 0 .. 6*WSZ-1
    const int WSZ = CC * CC;
    int j = i / WSZ, r = i - j * WSZ;
    const float* src = j == 0 ? w0 : j == 1 ? w1 : j == 2 ? w2 : j == 3 ? w3 : j == 4 ? w4 : w5;
    float v = src[r];
    __half hi = __float2half(v);
    g_wh[i] = hi;
    g_wl[i] = __float2half(v - __half2float(hi));
}

// ---------------- fp16 HMMA GEMM (2-product): C = A @ W^T -------------------
// CTA tile 128x128, BK=32, 4 warps (2x2), warp tile 64x64, 4-stage cp.async,
// 128 threads, 2 CTAs/SM.
// EPI: 0 = plain, 1 = sigmoid(x+bias), 2 = qkv (sel 0,1: L2 norm over N-tile
//      rows; sel 2: LayerNorm with vn_g/vn_b passed via bias0/bias1).
// For EPI=2 the N tile (128) equals the head dim, so each CTA owns full rows.
#define BKK     32
#define ROWA    80
#define ATILE_B (128*ROWA)         // 10240
#define BTILE_B (128*128)          // 16384
#define STAGEB  (ATILE_B+BTILE_B)  // 26624
#define STAGES  4
#define KTILES  (CC/BKK)           // 64
#define GEMM_SMEM (STAGES*STAGEB)  // 106496

template <int EPI>
__global__ void __launch_bounds__(128, 2)
gemm_multi(const __half* __restrict__ Ah,
           const __half* __restrict__ B0h, const __half* __restrict__ B0l,
           const __half* __restrict__ B1h, const __half* __restrict__ B1l,
           const __half* __restrict__ B2h, const __half* __restrict__ B2l,
           float* __restrict__ C0, float* __restrict__ C1, float* __restrict__ C2,
           const float* __restrict__ bias0, const float* __restrict__ bias1)
{
    extern __shared__ char smem[];
    const uint32_t sb = smem_u32(smem);
    const int sel = blockIdx.x >> 4;
    const __half* Bh = sel == 0 ? B0h : sel == 1 ? B1h : B2h;
    const __half* Bl = sel == 0 ? B0l : sel == 1 ? B1l : B2l;
    float* C = sel == 0 ? C0 : sel == 1 ? C1 : C2;

    const int tid = threadIdx.x;
    const int lane = tid & 31;
    const int wid = tid >> 5;
    const int bm = blockIdx.y * 128;
    const int bn = (blockIdx.x & 15) * 128;
    const int wm = (wid >> 1) * 64;   // 0 or 64
    const int wn = (wid & 1) * 64;    // 0 or 64

    float acc[4][8][4];
#pragma unroll
    for (int i = 0; i < 4; i++)
#pragma unroll
        for (int j = 0; j < 8; j++)
#pragma unroll
            for (int r = 0; r < 4; r++) acc[i][j][r] = 0.f;

    // ldmatrix per-thread address components
    const uint32_t xm = (uint32_t)((lane & 7) << 4);            // B swizzle xor
    const int arow = lane & 15;
    const uint32_t ahalf = (uint32_t)((lane >> 4) << 4);        // 0 or 16
    const int brow = (lane & 7) | ((lane >> 4) << 3);
    const uint32_t bhalf = (uint32_t)(((lane >> 3) & 1) << 4);  // 0 or 16

    auto load_stage = [&](int s, int kt) {
        uint32_t base = sb + s * STAGEB;
        int k0 = kt * BKK;
#pragma unroll
        for (int i = 0; i < 4; i++) {
            int u = tid + i * 128;          // 0..511
            int r = u >> 2, c = u & 3;
            cp16(base + r * ROWA + c * 16, Ah + (size_t)(bm + r) * CC + k0 + c * 8);
        }
#pragma unroll
        for (int i = 0; i < 8; i++) {
            int u = tid + i * 128;          // 0..1023
            int r = u >> 3, c = u & 7;
            const __half* src = ((c & 4) ? Bl : Bh) + (size_t)(bn + r) * CC + k0 + (c & 3) * 8;
            cp16(base + ATILE_B + r * 128 + ((uint32_t)(c * 16) ^ (uint32_t)((r & 7) << 4)), src);
        }
    };

    load_stage(0, 0); CP_COMMIT();
    load_stage(1, 1); CP_COMMIT();
    load_stage(2, 2); CP_COMMIT();

    for (int kt = 0; kt < KTILES; kt++) {
        if (kt <= KTILES - 3)      cp_wait<2>();
        else if (kt == KTILES - 2) cp_wait<1>();
        else                       cp_wait<0>();
        __syncthreads();
        if (kt + 3 < KTILES) { load_stage((kt + 3) % STAGES, kt + 3); CP_COMMIT(); }

        const uint32_t st = sb + (kt % STAGES) * STAGEB;
        const uint32_t aBase = st + (uint32_t)((wm + arow) * ROWA);
        const uint32_t bBase = st + ATILE_B + (uint32_t)((wn + brow) * 128);
#pragma unroll
        for (int ks = 0; ks < 2; ks++) {
            uint32_t ah[4][4];
            const uint32_t aoff = (uint32_t)(ks * 32) + ahalf;
#pragma unroll
            for (int mi = 0; mi < 4; mi++)
                ldsm4(ah[mi], aBase + mi * 16 * ROWA + aoff);
            const uint32_t boff_h = ((uint32_t)(ks * 32) + bhalf) ^ xm;
            const uint32_t boff_l = ((uint32_t)(ks * 32) + bhalf + 64) ^ xm;
#pragma unroll
            for (int jj = 0; jj < 4; jj++) {
                uint32_t bh[4], bl[4];
                ldsm4(bh, bBase + jj * 2048 + boff_h);
                ldsm4(bl, bBase + jj * 2048 + boff_l);
#pragma unroll
                for (int mi = 0; mi < 4; mi++) {
                    mma_f16(acc[mi][2*jj],   ah[mi], bh);
                    mma_f16(acc[mi][2*jj+1], ah[mi], bh + 2);
                    mma_f16(acc[mi][2*jj],   ah[mi], bl);
                    mma_f16(acc[mi][2*jj+1], ah[mi], bl + 2);
                }
            }
        }
    }

    const int gr = lane >> 2, ti = lane & 3;

    if (EPI == 2) {
        // fused row-norm epilogue: per-row sum/sumsq over the 128-col tile
        float rs[8], rq[8];
#pragma unroll
        for (int mi = 0; mi < 4; mi++) {
#pragma unroll
            for (int half = 0; half < 2; half++) {
                float s = 0.f, ss = 0.f;
#pragma unroll
                for (int j = 0; j < 8; j++) {
                    float a0 = acc[mi][j][half*2+0], a1 = acc[mi][j][half*2+1];
                    s += a0 + a1; ss += a0*a0 + a1*a1;
                }
                rs[mi*2+half] = s; rq[mi*2+half] = ss;
            }
        }
#pragma unroll
        for (int o = 1; o <= 2; o <<= 1) {
#pragma unroll
            for (int t = 0; t < 8; t++) {
                rs[t] += __shfl_xor_sync(0xFFFFFFFFu, rs[t], o);
                rq[t] += __shfl_xor_sync(0xFFFFFFFFu, rq[t], o);
            }
        }
        float* ssum = (float*)smem;         // [128][2]
        float* sss  = ssum + 256;           // [128][2]
        __syncthreads();
        if (ti == 0) {
#pragma unroll
            for (int t = 0; t < 8; t++) {
                int row = wm + (t >> 1) * 16 + (t & 1) * 8 + gr;
                int wc = wid & 1;
                ssum[row * 2 + wc] = rs[t];
                sss [row * 2 + wc] = rq[t];
            }
        }
        __syncthreads();
#pragma unroll
        for (int mi = 0; mi < 4; mi++) {
#pragma unroll
            for (int half = 0; half < 2; half++) {
                int row = wm + mi * 16 + half * 8 + gr;
                int m0 = bm + row;
                float S = ssum[row*2] + ssum[row*2+1];
                float Q = sss [row*2] + sss [row*2+1];
                if (sel < 2) {
                    float inv = 1.f / fmaxf(sqrtf(Q), 1e-12f);
#pragma unroll
                    for (int j = 0; j < 8; j++) {
                        int col = bn + wn + j * 8 + ti * 2;
                        float2 v = make_float2(acc[mi][j][half*2] * inv,
                                               acc[mi][j][half*2+1] * inv);
                        *(float2*)(C + (size_t)m0 * CC + col) = v;
                    }
                } else {
                    float mean = S * (1.f / 128.f);
                    float rr = rsqrtf(Q * (1.f / 128.f) - mean * mean + 1e-5f);
#pragma unroll
                    for (int j = 0; j < 8; j++) {
                        int d = wn + j * 8 + ti * 2;
                        int col = bn + d;
                        float2 v;
                        v.x = (acc[mi][j][half*2]   - mean) * rr * bias0[d]   + bias1[d];
                        v.y = (acc[mi][j][half*2+1] - mean) * rr * bias0[d+1] + bias1[d+1];
                        *(float2*)(C + (size_t)m0 * CC + col) = v;
                    }
                }
            }
        }
    } else {
        const float* bias = (sel == 0) ? bias0 : bias1;
#pragma unroll
        for (int mi = 0; mi < 4; mi++) {
            int m0 = bm + wm + mi * 16 + gr;
#pragma unroll
            for (int j = 0; j < 8; j++) {
                int col = bn + wn + j * 8 + ti * 2;
                float2 v0 = make_float2(acc[mi][j][0], acc[mi][j][1]);
                float2 v1 = make_float2(acc[mi][j][2], acc[mi][j][3]);
                if (EPI == 1) {
                    float b0 = bias[col], b1 = bias[col + 1];
                    v0.x = sigmoidf(v0.x + b0); v0.y = sigmoidf(v0.y + b1);
                    v1.x = sigmoidf(v1.x + b0); v1.y = sigmoidf(v1.y + b1);
                }
                *(float2*)(C + (size_t)m0 * CC + col) = v0;
                *(float2*)(C + (size_t)(m0 + 8) * CC + col) = v1;
            }
        }
    }
}

// ------- causal depthwise conv (K=4) + SiLU + fp16 casts (xc and x) --------
__global__ void conv_silu_kernel(const float* __restrict__ x,
                                 const float* __restrict__ w,
                                 const float* __restrict__ b) {
    int idx = blockIdx.x * blockDim.x + threadIdx.x;
    if (idx >= NTOT) return;
    int c = idx & (CC - 1);
    int t = (idx / CC) & (TT - 1);
    float acc = b[c];
    const float* wc = w + c * KK;
    float xcur = 0.f;
#pragma unroll
    for (int j = 0; j < KK; j++) {
        int tt = t - (KK - 1) + j;
        if (tt >= 0) {
            float xv = x[idx + (j - (KK - 1)) * CC];
            if (j == KK - 1) xcur = xv;
            acc = fmaf(xv, wc[j], acc);
        }
    }
    float y = acc * sigmoidf(acc);
    g_xc[idx] = y;
    g_ch[idx] = __float2half(y);
    g_xh[idx] = __float2half(xcur);
}

// ------- gamma = sigmoid(xc @ gamma_w^T + gamma_b): 8 tokens per block -----
__global__ void gamma_kernel(const float* __restrict__ gw, const float* __restrict__ gb) {
    extern __shared__ float sx[];   // 8*CC floats = 64KB
    int t0 = blockIdx.x * 8;
    for (int i = threadIdx.x; i < 8 * CC; i += 256)
        sx[i] = g_xc[(size_t)t0 * CC + i];
    __syncthreads();
    int warp = threadIdx.x >> 5, lane = threadIdx.x & 31;   // warp = token
    const float* xr = sx + warp * CC;
#pragma unroll
    for (int h = 0; h < HH; h++) {
        const float* w = gw + (size_t)h * CC;
        float s = 0.f;
        for (int k = lane; k < CC; k += 32) s = fmaf(xr[k], w[k], s);
        s = warp_sum(s);
        if (lane == 0) g_gamma[(size_t)(t0 + warp) * HH + h] = sigmoidf(s + gb[h]);
    }
}

// ------- chunked scan pass A: kv = ig*k*v inline + local scan --------------
__global__ void scan_local_kernel() {
    int blk = blockIdx.x;
    int chunk = blk & (NCH - 1);
    int bh = blk / NCH;
    int b = bh / HH, h = bh % HH;
    int d = threadIdx.x;
    int t0 = chunk * CHL;
    size_t idx = ((size_t)(b * TT + t0) * HH + h) * DD + d;
    const float* gam = g_gamma + (size_t)(b * TT + t0) * HH + h;
    float* cumg = g_cumG + (size_t)bh * TT + t0;
    float mem = 0.f, cg = 1.f;
#pragma unroll 4
    for (int tt = 0; tt < CHL; tt++) {
        float g = __ldg(gam + (size_t)tt * HH);
        float kv = g_ig[idx] * g_k[idx] * g_v[idx];
        mem = fmaf(g, mem, kv);
        g_v[idx] = mem;
        cg *= g;
        if (d == 0) cumg[tt] = cg;
        idx += (size_t)HH * DD;
    }
    g_carry[(size_t)blk * DD + d] = mem;
}

// ---------------- chunked scan: pass B (combine carries) -------------------
__global__ void scan_carry_kernel() {
    int bh = blockIdx.x;
    int d = threadIdx.x;
    float p = 0.f;
    for (int c = 0; c < NCH; c++) {
        g_prefix[((size_t)bh * NCH + c) * DD + d] = p;
        float G = g_cumG[(size_t)bh * TT + c * CHL + CHL - 1];
        p = g_carry[((size_t)bh * NCH + c) * DD + d] + G * p;
    }
}

// -------- prefix apply + LN(mem)*q -> GroupNorm -> *og -> fp16 cast --------
__global__ void post_kernel(const float* __restrict__ mn_g, const float* __restrict__ mn_b,
                            const float* __restrict__ gn_g, const float* __restrict__ gn_b) {
    int row = (blockIdx.x * blockDim.x + threadIdx.x) >> 5;
    int lane = threadIdx.x & 31;
    if (row >= NTOK * HH) return;
    size_t off = (size_t)row * DD + lane * 4;
    float4 m  = *(const float4*)(g_v + off);
    float4 q  = *(const float4*)(g_q + off);
    float4 og = *(const float4*)(g_og + off);

    int b = row / (TT * HH);
    int t = (row / HH) & (TT - 1);
    int h = row & (HH - 1);
    int bh = b * HH + h;
    int chunk = t / CHL;
    float cg = g_cumG[(size_t)bh * TT + t];
    float4 pf = *(const float4*)(g_prefix + ((size_t)bh * NCH + chunk) * DD + lane * 4);
    m.x = fmaf(pf.x, cg, m.x);
    m.y = fmaf(pf.y, cg, m.y);
    m.z = fmaf(pf.z, cg, m.z);
    m.w = fmaf(pf.w, cg, m.w);

    float s = m.x + m.y + m.z + m.w;
    float ss = m.x * m.x + m.y * m.y + m.z * m.z + m.w * m.w;
    s = warp_sum(s); ss = warp_sum(ss);
    float mean = s * (1.f / DD);
    float var = ss * (1.f / DD) - mean * mean;
    float r = rsqrtf(var + 1e-5f);
    int d = lane * 4;
    float4 o1;
    o1.x = ((m.x - mean) * r * mn_g[d + 0] + mn_b[d + 0]) * q.x;
    o1.y = ((m.y - mean) * r * mn_g[d + 1] + mn_b[d + 1]) * q.y;
    o1.z = ((m.z - mean) * r * mn_g[d + 2] + mn_b[d + 2]) * q.z;
    o1.w = ((m.w - mean) * r * mn_g[d + 3] + mn_b[d + 3]) * q.w;

    float s2 = o1.x + o1.y + o1.z + o1.w;
    float ss2 = o1.x * o1.x + o1.y * o1.y + o1.z * o1.z + o1.w * o1.w;
    s2 = warp_sum(s2); ss2 = warp_sum(ss2);
    float mean2 = s2 * (1.f / DD);
    float var2 = ss2 * (1.f / DD) - mean2 * mean2;
    float r2 = rsqrtf(var2 + 1e-5f);
    int c = h * DD + d;
    float ov0 = (((o1.x - mean2) * r2) * gn_g[c + 0] + gn_b[c + 0]) * og.x;
    float ov1 = (((o1.y - mean2) * r2) * gn_g[c + 1] + gn_b[c + 1]) * og.y;
    float ov2 = (((o1.z - mean2) * r2) * gn_g[c + 2] + gn_b[c + 2]) * og.z;
    float ov3 = (((o1.w - mean2) * r2) * gn_g[c + 3] + gn_b[c + 3]) * og.w;
    __half2* dst = (__half2*)(g_oh + off);
    dst[0] = __floats2half2_rn(ov0, ov1);
    dst[1] = __floats2half2_rn(ov2, ov3);
}

// ---------------- launch ----------------------------------------------------
extern "C" void kernel_launch(void* const* d_in, const int* in_sizes, int n_in,
                              void* d_out, int out_size) {
    const float* x       = (const float*)d_in[0];
    const float* Wq      = (const float*)d_in[1];
    const float* Wk      = (const float*)d_in[2];
    const float* Wv      = (const float*)d_in[3];
    const float* Wo      = (const float*)d_in[4];
    const float* conv_w  = (const float*)d_in[5];
    const float* conv_b  = (const float*)d_in[6];
    const float* ig_w    = (const float*)d_in[7];
    const float* ig_b    = (const float*)d_in[8];
    const float* og_w    = (const float*)d_in[9];
    const float* og_b    = (const float*)d_in[10];
    const float* gamma_w = (const float*)d_in[11];
    const float* gamma_b = (const float*)d_in[12];
    const float* vn_g    = (const float*)d_in[13];
    const float* vn_b    = (const float*)d_in[14];
    const float* gn_g    = (const float*)d_in[15];
    const float* gn_b    = (const float*)d_in[16];
    const float* mn_g    = (const float*)d_in[17];
    const float* mn_b    = (const float*)d_in[18];
    float* out = (float*)d_out;

    float *p_q, *p_k, *p_v, *p_ig, *p_og;
    cudaGetSymbolAddress((void**)&p_q,  g_q);
    cudaGetSymbolAddress((void**)&p_k,  g_k);
    cudaGetSymbolAddress((void**)&p_v,  g_v);
    cudaGetSymbolAddress((void**)&p_ig, g_ig);
    cudaGetSymbolAddress((void**)&p_og, g_og);

    __half *p_xh, *p_ch, *p_oh, *p_wh, *p_wl;
    cudaGetSymbolAddress((void**)&p_xh, g_xh);
    cudaGetSymbolAddress((void**)&p_ch, g_ch);
    cudaGetSymbolAddress((void**)&p_oh, g_oh);
    cudaGetSymbolAddress((void**)&p_wh, g_wh);
    cudaGetSymbolAddress((void**)&p_wl, g_wl);

    cudaFuncSetAttribute(gemm_multi<0>, cudaFuncAttributeMaxDynamicSharedMemorySize, GEMM_SMEM);
    cudaFuncSetAttribute(gemm_multi<1>, cudaFuncAttributeMaxDynamicSharedMemorySize, GEMM_SMEM);
    cudaFuncSetAttribute(gemm_multi<2>, cudaFuncAttributeMaxDynamicSharedMemorySize, GEMM_SMEM);
    cudaFuncSetAttribute(gamma_kernel, cudaFuncAttributeMaxDynamicSharedMemorySize, 8 * CC * 4);

    const size_t WSZ = (size_t)CC * CC;   // 4M elems per weight matrix

    conv_silu_kernel<<<NTOT / 256, 256>>>(x, conv_w, conv_b);
    cvt_w_kernel<<<(6 * (int)WSZ) / 256, 256>>>(Wq, Wk, Wv, ig_w, og_w, Wo);

    // q, k, v fused; epilogue: q,k L2-norm, v LayerNorm (vn via bias args)
    {
        dim3 grid(48, NTOK / 128);
        gemm_multi<2><<<grid, 128, GEMM_SMEM>>>(p_xh,
            p_wh + 0*WSZ, p_wl + 0*WSZ, p_wh + 1*WSZ, p_wl + 1*WSZ, p_wh + 2*WSZ, p_wl + 2*WSZ,
            p_q, p_k, p_v, vn_g, vn_b);
    }
    // ig, og fused (with sigmoid+bias epilogue)
    {
        dim3 grid(32, NTOK / 128);
        gemm_multi<1><<<grid, 128, GEMM_SMEM>>>(p_ch,
            p_wh + 3*WSZ, p_wl + 3*WSZ, p_wh + 4*WSZ, p_wl + 4*WSZ, p_wh + 4*WSZ, p_wl + 4*WSZ,
            p_ig, p_og, p_og, ig_b, og_b);
    }

    gamma_kernel<<<NTOK / 8, 256, 8 * CC * 4>>>(gamma_w, gamma_b);

    scan_local_kernel<<<BB * HH * NCH, DD>>>();
    scan_carry_kernel<<<BB * HH, DD>>>();

    int nrows = NTOK * HH;                       // 131072 rows of 128
    int rblocks = nrows / 8;
    post_kernel<<<rblocks, 256>>>(mn_g, mn_b, gn_g, gn_b);

    // final projection
    {
        dim3 grid(16, NTOK / 128);
        gemm_multi<0><<<grid, 128, GEMM_SMEM>>>(p_oh,
            p_wh + 5*WSZ, p_wl + 5*WSZ, p_wh + 5*WSZ, p_wl + 5*WSZ, p_wh + 5*WSZ, p_wl + 5*WSZ,
            out, out, out, nullptr, nullptr);
    }
}

// round 11
// speedup vs baseline: 4.9950x; 1.2048x over previous
#include <cuda_runtime.h>
#include <cuda_fp16.h>
#include <math.h>
#include <stdint.h>

// Problem constants
#define BB 2
#define TT 4096
#define CC 2048
#define HH 16
#define DD 128
#define KK 4
#define NTOK (BB*TT)          // 8192 tokens
#define NTOT (BB*TT*CC)       // 16777216 elements
#define NCH  32               // scan chunks
#define CHL  (TT/NCH)         // 128 timesteps per chunk

// ---------------- scratch (device globals: allocation-free) ----------------
__device__ float g_xc[NTOT];      // conv+silu output (fp32, feeds gamma GEMM)
__device__ float g_q [NTOT];      // q (L2-normalized in GEMM epilogue)
__device__ float g_k [NTOT];      // k (L2-normalized in GEMM epilogue)
__device__ float g_v [NTOT];      // v (LayerNormed) -> local mem (in place)
__device__ float g_ig[NTOT];
__device__ float g_og[NTOT];
__device__ float g_gamma[NTOK*HH];
__device__ float g_cumG[BB*HH*TT];          // per-chunk cumulative gamma
__device__ float g_carry[BB*HH*NCH*DD];     // chunk-final local mem
__device__ float g_prefix[BB*HH*NCH*DD];    // incoming prefix per chunk

// fp16 buffers (A-side: hi only; weights: hi+lo)
__device__ __half g_xh[NTOT];               // x (hi)
__device__ __half g_ch[NTOT];               // xc (hi)
__device__ __half g_oh[NTOT];               // gated output (hi)
__device__ __half g_wh[6*CC*CC], g_wl[6*CC*CC]; // Wq,Wk,Wv,ig_w,og_w,Wo

// ---------------- helpers ----------------
__device__ __forceinline__ float warp_sum(float v) {
#pragma unroll
    for (int o = 16; o; o >>= 1) v += __shfl_xor_sync(0xFFFFFFFFu, v, o);
    return v;
}
__device__ __forceinline__ float sigmoidf(float x) { return 1.f / (1.f + expf(-x)); }

__device__ __forceinline__ uint32_t smem_u32(const void* p) {
    uint32_t a;
    asm("{ .reg .u64 t; cvta.to.shared.u64 t, %1; cvt.u32.u64 %0, t; }" : "=r"(a) : "l"(p));
    return a;
}
__device__ __forceinline__ void cp16(uint32_t dst, const void* src) {
    asm volatile("cp.async.cg.shared.global [%0], [%1], 16;" :: "r"(dst), "l"(src));
}
#define CP_COMMIT() asm volatile("cp.async.commit_group;" ::: "memory")
template <int N>
__device__ __forceinline__ void cp_wait() { asm volatile("cp.async.wait_group %0;" :: "n"(N) : "memory"); }

__device__ __forceinline__ void ldsm4(uint32_t* r, uint32_t addr) {
    asm volatile("ldmatrix.sync.aligned.m8n8.x4.shared.b16 {%0,%1,%2,%3}, [%4];"
                 : "=r"(r[0]), "=r"(r[1]), "=r"(r[2]), "=r"(r[3]) : "r"(addr));
}
__device__ __forceinline__ void mma_f16(float* c, const uint32_t* a, const uint32_t* b) {
    asm volatile(
        "mma.sync.aligned.m16n8k16.row.col.f32.f16.f16.f32 "
        "{%0,%1,%2,%3}, {%4,%5,%6,%7}, {%8,%9}, {%0,%1,%2,%3};"
        : "+f"(c[0]), "+f"(c[1]), "+f"(c[2]), "+f"(c[3])
        : "r"(a[0]), "r"(a[1]), "r"(a[2]), "r"(a[3]), "r"(b[0]), "r"(b[1]));
}

// split all 6 weight matrices in one launch
__global__ void cvt_w_kernel(const float* __restrict__ w0, const float* __restrict__ w1,
                             const float* __restrict__ w2, const float* __restrict__ w3,
                             const float* __restrict__ w4, const float* __restrict__ w5) {
    int i = blockIdx.x * blockDim.x + threadIdx.x;           // 0 .. 6*WSZ-1
    const int WSZ = CC * CC;
    int j = i / WSZ, r = i - j * WSZ;
    const float* src = j == 0 ? w0 : j == 1 ? w1 : j == 2 ? w2 : j == 3 ? w3 : j == 4 ? w4 : w5;
    float v = src[r];
    __half hi = __float2half(v);
    g_wh[i] = hi;
    g_wl[i] = __float2half(v - __half2float(hi));
}

// ---------------- fp16 HMMA GEMM: C = A @ W^T -------------------------------
// CTA tile 128x128, BK=32, 4 warps (2x2), warp tile 64x64, 4-stage cp.async,
// 128 threads, 2 CTAs/SM.
// EPI: 0 = plain, 1 = sigmoid(x+bias), 2 = qkv (sel 0,1: L2 norm; sel 2: LN).
// NPROD: 2 = Ah*Bh + Ah*Bl (weight hi+lo correction), 1 = Ah*Bh only.
#define BKK     32
#define ROWA    80
#define ATILE_B (128*ROWA)         // 10240
#define BTILE_B (128*128)          // 16384
#define STAGEB  (ATILE_B+BTILE_B)  // 26624
#define STAGES  4
#define KTILES  (CC/BKK)           // 64
#define GEMM_SMEM (STAGES*STAGEB)  // 106496

template <int EPI, int NPROD>
__global__ void __launch_bounds__(128, 2)
gemm_multi(const __half* __restrict__ Ah,
           const __half* __restrict__ B0h, const __half* __restrict__ B0l,
           const __half* __restrict__ B1h, const __half* __restrict__ B1l,
           const __half* __restrict__ B2h, const __half* __restrict__ B2l,
           float* __restrict__ C0, float* __restrict__ C1, float* __restrict__ C2,
           const float* __restrict__ bias0, const float* __restrict__ bias1)
{
    extern __shared__ char smem[];
    const uint32_t sb = smem_u32(smem);
    const int sel = blockIdx.x >> 4;
    const __half* Bh = sel == 0 ? B0h : sel == 1 ? B1h : B2h;
    const __half* Bl = sel == 0 ? B0l : sel == 1 ? B1l : B2l;
    float* C = sel == 0 ? C0 : sel == 1 ? C1 : C2;

    const int tid = threadIdx.x;
    const int lane = tid & 31;
    const int wid = tid >> 5;
    const int bm = blockIdx.y * 128;
    const int bn = (blockIdx.x & 15) * 128;
    const int wm = (wid >> 1) * 64;   // 0 or 64
    const int wn = (wid & 1) * 64;    // 0 or 64

    float acc[4][8][4];
#pragma unroll
    for (int i = 0; i < 4; i++)
#pragma unroll
        for (int j = 0; j < 8; j++)
#pragma unroll
            for (int r = 0; r < 4; r++) acc[i][j][r] = 0.f;

    // ldmatrix per-thread address components
    const uint32_t xm = (uint32_t)((lane & 7) << 4);            // B swizzle xor
    const int arow = lane & 15;
    const uint32_t ahalf = (uint32_t)((lane >> 4) << 4);        // 0 or 16
    const int brow = (lane & 7) | ((lane >> 4) << 3);
    const uint32_t bhalf = (uint32_t)(((lane >> 3) & 1) << 4);  // 0 or 16

    auto load_stage = [&](int s, int kt) {
        uint32_t base = sb + s * STAGEB;
        int k0 = kt * BKK;
#pragma unroll
        for (int i = 0; i < 4; i++) {
            int u = tid + i * 128;          // 0..511
            int r = u >> 2, c = u & 3;
            cp16(base + r * ROWA + c * 16, Ah + (size_t)(bm + r) * CC + k0 + c * 8);
        }
        if (NPROD == 2) {
#pragma unroll
            for (int i = 0; i < 8; i++) {
                int u = tid + i * 128;      // 0..1023
                int r = u >> 3, c = u & 7;
                const __half* src = ((c & 4) ? Bl : Bh) + (size_t)(bn + r) * CC + k0 + (c & 3) * 8;
                cp16(base + ATILE_B + r * 128 + ((uint32_t)(c * 16) ^ (uint32_t)((r & 7) << 4)), src);
            }
        } else {
#pragma unroll
            for (int i = 0; i < 4; i++) {
                int u = tid + i * 128;      // 0..511 -> hi half only
                int r = u >> 2, c = u & 3;
                const __half* src = Bh + (size_t)(bn + r) * CC + k0 + c * 8;
                cp16(base + ATILE_B + r * 128 + ((uint32_t)(c * 16) ^ (uint32_t)((r & 7) << 4)), src);
            }
        }
    };

    load_stage(0, 0); CP_COMMIT();
    load_stage(1, 1); CP_COMMIT();
    load_stage(2, 2); CP_COMMIT();

    for (int kt = 0; kt < KTILES; kt++) {
        if (kt <= KTILES - 3)      cp_wait<2>();
        else if (kt == KTILES - 2) cp_wait<1>();
        else                       cp_wait<0>();
        __syncthreads();
        if (kt + 3 < KTILES) { load_stage((kt + 3) % STAGES, kt + 3); CP_COMMIT(); }

        const uint32_t st = sb + (kt % STAGES) * STAGEB;
        const uint32_t aBase = st + (uint32_t)((wm + arow) * ROWA);
        const uint32_t bBase = st + ATILE_B + (uint32_t)((wn + brow) * 128);
#pragma unroll
        for (int ks = 0; ks < 2; ks++) {
            uint32_t ah[4][4];
            const uint32_t aoff = (uint32_t)(ks * 32) + ahalf;
#pragma unroll
            for (int mi = 0; mi < 4; mi++)
                ldsm4(ah[mi], aBase + mi * 16 * ROWA + aoff);
            const uint32_t boff_h = ((uint32_t)(ks * 32) + bhalf) ^ xm;
            const uint32_t boff_l = ((uint32_t)(ks * 32) + bhalf + 64) ^ xm;
#pragma unroll
            for (int jj = 0; jj < 4; jj++) {
                uint32_t bh[4], bl[4];
                ldsm4(bh, bBase + jj * 2048 + boff_h);
                if (NPROD == 2) ldsm4(bl, bBase + jj * 2048 + boff_l);
#pragma unroll
                for (int mi = 0; mi < 4; mi++) {
                    mma_f16(acc[mi][2*jj],   ah[mi], bh);
                    mma_f16(acc[mi][2*jj+1], ah[mi], bh + 2);
                    if (NPROD == 2) {
                        mma_f16(acc[mi][2*jj],   ah[mi], bl);
                        mma_f16(acc[mi][2*jj+1], ah[mi], bl + 2);
                    }
                }
            }
        }
    }

    const int gr = lane >> 2, ti = lane & 3;

    if (EPI == 2) {
        // fused row-norm epilogue: per-row sum/sumsq over the 128-col tile
        float rs[8], rq[8];
#pragma unroll
        for (int mi = 0; mi < 4; mi++) {
#pragma unroll
            for (int half = 0; half < 2; half++) {
                float s = 0.f, ss = 0.f;
#pragma unroll
                for (int j = 0; j < 8; j++) {
                    float a0 = acc[mi][j][half*2+0], a1 = acc[mi][j][half*2+1];
                    s += a0 + a1; ss += a0*a0 + a1*a1;
                }
                rs[mi*2+half] = s; rq[mi*2+half] = ss;
            }
        }
#pragma unroll
        for (int o = 1; o <= 2; o <<= 1) {
#pragma unroll
            for (int t = 0; t < 8; t++) {
                rs[t] += __shfl_xor_sync(0xFFFFFFFFu, rs[t], o);
                rq[t] += __shfl_xor_sync(0xFFFFFFFFu, rq[t], o);
            }
        }
        float* ssum = (float*)smem;         // [128][2]
        float* sss  = ssum + 256;           // [128][2]
        __syncthreads();
        if (ti == 0) {
#pragma unroll
            for (int t = 0; t < 8; t++) {
                int row = wm + (t >> 1) * 16 + (t & 1) * 8 + gr;
                int wc = wid & 1;
                ssum[row * 2 + wc] = rs[t];
                sss [row * 2 + wc] = rq[t];
            }
        }
        __syncthreads();
#pragma unroll
        for (int mi = 0; mi < 4; mi++) {
#pragma unroll
            for (int half = 0; half < 2; half++) {
                int row = wm + mi * 16 + half * 8 + gr;
                int m0 = bm + row;
                float S = ssum[row*2] + ssum[row*2+1];
                float Q = sss [row*2] + sss [row*2+1];
                if (sel < 2) {
                    float inv = 1.f / fmaxf(sqrtf(Q), 1e-12f);
#pragma unroll
                    for (int j = 0; j < 8; j++) {
                        int col = bn + wn + j * 8 + ti * 2;
                        float2 v = make_float2(acc[mi][j][half*2] * inv,
                                               acc[mi][j][half*2+1] * inv);
                        *(float2*)(C + (size_t)m0 * CC + col) = v;
                    }
                } else {
                    float mean = S * (1.f / 128.f);
                    float rr = rsqrtf(Q * (1.f / 128.f) - mean * mean + 1e-5f);
#pragma unroll
                    for (int j = 0; j < 8; j++) {
                        int d = wn + j * 8 + ti * 2;
                        int col = bn + d;
                        float2 v;
                        v.x = (acc[mi][j][half*2]   - mean) * rr * bias0[d]   + bias1[d];
                        v.y = (acc[mi][j][half*2+1] - mean) * rr * bias0[d+1] + bias1[d+1];
                        *(float2*)(C + (size_t)m0 * CC + col) = v;
                    }
                }
            }
        }
    } else {
        const float* bias = (sel == 0) ? bias0 : bias1;
#pragma unroll
        for (int mi = 0; mi < 4; mi++) {
            int m0 = bm + wm + mi * 16 + gr;
#pragma unroll
            for (int j = 0; j < 8; j++) {
                int col = bn + wn + j * 8 + ti * 2;
                float2 v0 = make_float2(acc[mi][j][0], acc[mi][j][1]);
                float2 v1 = make_float2(acc[mi][j][2], acc[mi][j][3]);
                if (EPI == 1) {
                    float b0 = bias[col], b1 = bias[col + 1];
                    v0.x = sigmoidf(v0.x + b0); v0.y = sigmoidf(v0.y + b1);
                    v1.x = sigmoidf(v1.x + b0); v1.y = sigmoidf(v1.y + b1);
                }
                *(float2*)(C + (size_t)m0 * CC + col) = v0;
                *(float2*)(C + (size_t)(m0 + 8) * CC + col) = v1;
            }
        }
    }
}

// ------- causal depthwise conv (K=4) + SiLU + fp16 casts (xc and x) --------
__global__ void conv_silu_kernel(const float* __restrict__ x,
                                 const float* __restrict__ w,
                                 const float* __restrict__ b) {
    int idx = blockIdx.x * blockDim.x + threadIdx.x;
    if (idx >= NTOT) return;
    int c = idx & (CC - 1);
    int t = (idx / CC) & (TT - 1);
    float acc = b[c];
    const float* wc = w + c * KK;
    float xcur = 0.f;
#pragma unroll
    for (int j = 0; j < KK; j++) {
        int tt = t - (KK - 1) + j;
        if (tt >= 0) {
            float xv = x[idx + (j - (KK - 1)) * CC];
            if (j == KK - 1) xcur = xv;
            acc = fmaf(xv, wc[j], acc);
        }
    }
    float y = acc * sigmoidf(acc);
    g_xc[idx] = y;
    g_ch[idx] = __float2half(y);
    g_xh[idx] = __float2half(xcur);
}

// ------- gamma = sigmoid(xc @ gamma_w^T + gamma_b): 8 tokens per block -----
__global__ void gamma_kernel(const float* __restrict__ gw, const float* __restrict__ gb) {
    extern __shared__ float sx[];   // 8*CC floats = 64KB
    int t0 = blockIdx.x * 8;
    for (int i = threadIdx.x; i < 8 * CC; i += 256)
        sx[i] = g_xc[(size_t)t0 * CC + i];
    __syncthreads();
    int warp = threadIdx.x >> 5, lane = threadIdx.x & 31;   // warp = token
    const float* xr = sx + warp * CC;
#pragma unroll
    for (int h = 0; h < HH; h++) {
        const float* w = gw + (size_t)h * CC;
        float s = 0.f;
        for (int k = lane; k < CC; k += 32) s = fmaf(xr[k], w[k], s);
        s = warp_sum(s);
        if (lane == 0) g_gamma[(size_t)(t0 + warp) * HH + h] = sigmoidf(s + gb[h]);
    }
}

// ------- chunked scan pass A: kv = ig*k*v inline + local scan --------------
__global__ void scan_local_kernel() {
    int blk = blockIdx.x;
    int chunk = blk & (NCH - 1);
    int bh = blk / NCH;
    int b = bh / HH, h = bh % HH;
    int d = threadIdx.x;
    int t0 = chunk * CHL;
    size_t idx = ((size_t)(b * TT + t0) * HH + h) * DD + d;
    const float* gam = g_gamma + (size_t)(b * TT + t0) * HH + h;
    float* cumg = g_cumG + (size_t)bh * TT + t0;
    float mem = 0.f, cg = 1.f;
#pragma unroll 4
    for (int tt = 0; tt < CHL; tt++) {
        float g = __ldg(gam + (size_t)tt * HH);
        float kv = g_ig[idx] * g_k[idx] * g_v[idx];
        mem = fmaf(g, mem, kv);
        g_v[idx] = mem;
        cg *= g;
        if (d == 0) cumg[tt] = cg;
        idx += (size_t)HH * DD;
    }
    g_carry[(size_t)blk * DD + d] = mem;
}

// ---------------- chunked scan: pass B (combine carries) -------------------
__global__ void scan_carry_kernel() {
    int bh = blockIdx.x;
    int d = threadIdx.x;
    float p = 0.f;
    for (int c = 0; c < NCH; c++) {
        g_prefix[((size_t)bh * NCH + c) * DD + d] = p;
        float G = g_cumG[(size_t)bh * TT + c * CHL + CHL - 1];
        p = g_carry[((size_t)bh * NCH + c) * DD + d] + G * p;
    }
}

// -------- prefix apply + LN(mem)*q -> GroupNorm -> *og -> fp16 cast --------
__global__ void post_kernel(const float* __restrict__ mn_g, const float* __restrict__ mn_b,
                            const float* __restrict__ gn_g, const float* __restrict__ gn_b) {
    int row = (blockIdx.x * blockDim.x + threadIdx.x) >> 5;
    int lane = threadIdx.x & 31;
    if (row >= NTOK * HH) return;
    size_t off = (size_t)row * DD + lane * 4;
    float4 m  = *(const float4*)(g_v + off);
    float4 q  = *(const float4*)(g_q + off);
    float4 og = *(const float4*)(g_og + off);

    int b = row / (TT * HH);
    int t = (row / HH) & (TT - 1);
    int h = row & (HH - 1);
    int bh = b * HH + h;
    int chunk = t / CHL;
    float cg = g_cumG[(size_t)bh * TT + t];
    float4 pf = *(const float4*)(g_prefix + ((size_t)bh * NCH + chunk) * DD + lane * 4);
    m.x = fmaf(pf.x, cg, m.x);
    m.y = fmaf(pf.y, cg, m.y);
    m.z = fmaf(pf.z, cg, m.z);
    m.w = fmaf(pf.w, cg, m.w);

    float s = m.x + m.y + m.z + m.w;
    float ss = m.x * m.x + m.y * m.y + m.z * m.z + m.w * m.w;
    s = warp_sum(s); ss = warp_sum(ss);
    float mean = s * (1.f / DD);
    float var = ss * (1.f / DD) - mean * mean;
    float r = rsqrtf(var + 1e-5f);
    int d = lane * 4;
    float4 o1;
    o1.x = ((m.x - mean) * r * mn_g[d + 0] + mn_b[d + 0]) * q.x;
    o1.y = ((m.y - mean) * r * mn_g[d + 1] + mn_b[d + 1]) * q.y;
    o1.z = ((m.z - mean) * r * mn_g[d + 2] + mn_b[d + 2]) * q.z;
    o1.w = ((m.w - mean) * r * mn_g[d + 3] + mn_b[d + 3]) * q.w;

    float s2 = o1.x + o1.y + o1.z + o1.w;
    float ss2 = o1.x * o1.x + o1.y * o1.y + o1.z * o1.z + o1.w * o1.w;
    s2 = warp_sum(s2); ss2 = warp_sum(ss2);
    float mean2 = s2 * (1.f / DD);
    float var2 = ss2 * (1.f / DD) - mean2 * mean2;
    float r2 = rsqrtf(var2 + 1e-5f);
    int c = h * DD + d;
    float ov0 = (((o1.x - mean2) * r2) * gn_g[c + 0] + gn_b[c + 0]) * og.x;
    float ov1 = (((o1.y - mean2) * r2) * gn_g[c + 1] + gn_b[c + 1]) * og.y;
    float ov2 = (((o1.z - mean2) * r2) * gn_g[c + 2] + gn_b[c + 2]) * og.z;
    float ov3 = (((o1.w - mean2) * r2) * gn_g[c + 3] + gn_b[c + 3]) * og.w;
    __half2* dst = (__half2*)(g_oh + off);
    dst[0] = __floats2half2_rn(ov0, ov1);
    dst[1] = __floats2half2_rn(ov2, ov3);
}

// ---------------- launch ----------------------------------------------------
extern "C" void kernel_launch(void* const* d_in, const int* in_sizes, int n_in,
                              void* d_out, int out_size) {
    const float* x       = (const float*)d_in[0];
    const float* Wq      = (const float*)d_in[1];
    const float* Wk      = (const float*)d_in[2];
    const float* Wv      = (const float*)d_in[3];
    const float* Wo      = (const float*)d_in[4];
    const float* conv_w  = (const float*)d_in[5];
    const float* conv_b  = (const float*)d_in[6];
    const float* ig_w    = (const float*)d_in[7];
    const float* ig_b    = (const float*)d_in[8];
    const float* og_w    = (const float*)d_in[9];
    const float* og_b    = (const float*)d_in[10];
    const float* gamma_w = (const float*)d_in[11];
    const float* gamma_b = (const float*)d_in[12];
    const float* vn_g    = (const float*)d_in[13];
    const float* vn_b    = (const float*)d_in[14];
    const float* gn_g    = (const float*)d_in[15];
    const float* gn_b    = (const float*)d_in[16];
    const float* mn_g    = (const float*)d_in[17];
    const float* mn_b    = (const float*)d_in[18];
    float* out = (float*)d_out;

    float *p_q, *p_k, *p_v, *p_ig, *p_og;
    cudaGetSymbolAddress((void**)&p_q,  g_q);
    cudaGetSymbolAddress((void**)&p_k,  g_k);
    cudaGetSymbolAddress((void**)&p_v,  g_v);
    cudaGetSymbolAddress((void**)&p_ig, g_ig);
    cudaGetSymbolAddress((void**)&p_og, g_og);

    __half *p_xh, *p_ch, *p_oh, *p_wh, *p_wl;
    cudaGetSymbolAddress((void**)&p_xh, g_xh);
    cudaGetSymbolAddress((void**)&p_ch, g_ch);
    cudaGetSymbolAddress((void**)&p_oh, g_oh);
    cudaGetSymbolAddress((void**)&p_wh, g_wh);
    cudaGetSymbolAddress((void**)&p_wl, g_wl);

    cudaFuncSetAttribute((const void*)gemm_multi<0,2>, cudaFuncAttributeMaxDynamicSharedMemorySize, GEMM_SMEM);
    cudaFuncSetAttribute((const void*)gemm_multi<1,1>, cudaFuncAttributeMaxDynamicSharedMemorySize, GEMM_SMEM);
    cudaFuncSetAttribute((const void*)gemm_multi<2,2>, cudaFuncAttributeMaxDynamicSharedMemorySize, GEMM_SMEM);
    cudaFuncSetAttribute(gamma_kernel, cudaFuncAttributeMaxDynamicSharedMemorySize, 8 * CC * 4);

    const size_t WSZ = (size_t)CC * CC;   // 4M elems per weight matrix

    // side stream + events for forked capture (created per call; few calls)
    cudaStream_t s1;
    cudaStreamCreateWithFlags(&s1, cudaStreamNonBlocking);
    cudaEvent_t e0, eW, eConv, eJoin;
    cudaEventCreateWithFlags(&e0,    cudaEventDisableTiming);
    cudaEventCreateWithFlags(&eW,    cudaEventDisableTiming);
    cudaEventCreateWithFlags(&eConv, cudaEventDisableTiming);
    cudaEventCreateWithFlags(&eJoin, cudaEventDisableTiming);

    // fork: cvt_w on s1 parallel with conv on default stream
    cudaEventRecord(e0, 0);
    cudaStreamWaitEvent(s1, e0, 0);
    cvt_w_kernel<<<(6 * (int)WSZ) / 256, 256, 0, s1>>>(Wq, Wk, Wv, ig_w, og_w, Wo);
    cudaEventRecord(eW, s1);

    conv_silu_kernel<<<NTOT / 256, 256>>>(x, conv_w, conv_b);
    cudaEventRecord(eConv, 0);

    // qkv on stream 0 (needs conv + cvt_w)
    cudaStreamWaitEvent(0, eW, 0);
    {
        dim3 grid(48, NTOK / 128);
        gemm_multi<2,2><<<grid, 128, GEMM_SMEM>>>(p_xh,
            p_wh + 0*WSZ, p_wl + 0*WSZ, p_wh + 1*WSZ, p_wl + 1*WSZ, p_wh + 2*WSZ, p_wl + 2*WSZ,
            p_q, p_k, p_v, vn_g, vn_b);
    }

    // ig/og (single-product) + gamma on s1, overlapping qkv
    cudaStreamWaitEvent(s1, eConv, 0);
    {
        dim3 grid(32, NTOK / 128);
        gemm_multi<1,1><<<grid, 128, GEMM_SMEM, s1>>>(p_ch,
            p_wh + 3*WSZ, p_wl + 3*WSZ, p_wh + 4*WSZ, p_wl + 4*WSZ, p_wh + 4*WSZ, p_wl + 4*WSZ,
            p_ig, p_og, p_og, ig_b, og_b);
    }
    gamma_kernel<<<NTOK / 8, 256, 8 * CC * 4, s1>>>(gamma_w, gamma_b);
    cudaEventRecord(eJoin, s1);
    cudaStreamWaitEvent(0, eJoin, 0);

    scan_local_kernel<<<BB * HH * NCH, DD>>>();
    scan_carry_kernel<<<BB * HH, DD>>>();

    int nrows = NTOK * HH;                       // 131072 rows of 128
    int rblocks = nrows / 8;
    post_kernel<<<rblocks, 256>>>(mn_g, mn_b, gn_g, gn_b);

    // final projection (2-product)
    {
        dim3 grid(16, NTOK / 128);
        gemm_multi<0,2><<<grid, 128, GEMM_SMEM>>>(p_oh,
            p_wh + 5*WSZ, p_wl + 5*WSZ, p_wh + 5*WSZ, p_wl + 5*WSZ, p_wh + 5*WSZ, p_wl + 5*WSZ,
            out, out, out, nullptr, nullptr);
    }
}

// round 12
// speedup vs baseline: 6.5998x; 1.3213x over previous
#include <cuda_runtime.h>
#include <cuda_fp16.h>
#include <math.h>
#include <stdint.h>

// Problem constants
#define BB 2
#define TT 4096
#define CC 2048
#define HH 16
#define DD 128
#define KK 4
#define NTOK (BB*TT)          // 8192 tokens
#define NTOT (BB*TT*CC)       // 16777216 elements
#define NCH  32               // scan chunks
#define CHL  (TT/NCH)         // 128 timesteps per chunk

// ---------------- scratch (device globals: allocation-free) ----------------
__device__ float g_xc[NTOT];      // conv+silu output (fp32, feeds gamma GEMM)
__device__ float g_q [NTOT];      // q (L2-normalized in GEMM epilogue)
__device__ float g_k [NTOT];      // k (L2-normalized in GEMM epilogue)
__device__ float g_v [NTOT];      // v (LayerNormed) -> local mem (in place)
__device__ float g_ig[NTOT];
__device__ float g_og[NTOT];
__device__ float g_gamma[NTOK*HH];
__device__ float g_cumG[BB*HH*TT];          // per-chunk cumulative gamma
__device__ float g_carry[BB*HH*NCH*DD];     // chunk-final local mem
__device__ float g_prefix[BB*HH*NCH*DD];    // incoming prefix per chunk

// fp16 buffers (hi-only everywhere; A-rounding dominates the error budget)
__device__ __half g_xh[NTOT];               // x
__device__ __half g_ch[NTOT];               // xc
__device__ __half g_oh[NTOT];               // gated output
__device__ __half g_wh[6*CC*CC];            // Wq,Wk,Wv,ig_w,og_w,Wo

// ---------------- helpers ----------------
__device__ __forceinline__ float warp_sum(float v) {
#pragma unroll
    for (int o = 16; o; o >>= 1) v += __shfl_xor_sync(0xFFFFFFFFu, v, o);
    return v;
}
__device__ __forceinline__ float sigmoidf(float x) { return 1.f / (1.f + expf(-x)); }

__device__ __forceinline__ uint32_t smem_u32(const void* p) {
    uint32_t a;
    asm("{ .reg .u64 t; cvta.to.shared.u64 t, %1; cvt.u32.u64 %0, t; }" : "=r"(a) : "l"(p));
    return a;
}
__device__ __forceinline__ void cp16(uint32_t dst, const void* src) {
    asm volatile("cp.async.cg.shared.global [%0], [%1], 16;" :: "r"(dst), "l"(src));
}
#define CP_COMMIT() asm volatile("cp.async.commit_group;" ::: "memory")
template <int N>
__device__ __forceinline__ void cp_wait() { asm volatile("cp.async.wait_group %0;" :: "n"(N) : "memory"); }

__device__ __forceinline__ void ldsm4(uint32_t* r, uint32_t addr) {
    asm volatile("ldmatrix.sync.aligned.m8n8.x4.shared.b16 {%0,%1,%2,%3}, [%4];"
                 : "=r"(r[0]), "=r"(r[1]), "=r"(r[2]), "=r"(r[3]) : "r"(addr));
}
__device__ __forceinline__ void mma_f16(float* c, const uint32_t* a, const uint32_t* b) {
    asm volatile(
        "mma.sync.aligned.m16n8k16.row.col.f32.f16.f16.f32 "
        "{%0,%1,%2,%3}, {%4,%5,%6,%7}, {%8,%9}, {%0,%1,%2,%3};"
        : "+f"(c[0]), "+f"(c[1]), "+f"(c[2]), "+f"(c[3])
        : "r"(a[0]), "r"(a[1]), "r"(a[2]), "r"(a[3]), "r"(b[0]), "r"(b[1]));
}

// cast all 6 weight matrices to fp16 in one launch
__global__ void cvt_w_kernel(const float* __restrict__ w0, const float* __restrict__ w1,
                             const float* __restrict__ w2, const float* __restrict__ w3,
                             const float* __restrict__ w4, const float* __restrict__ w5) {
    int i = blockIdx.x * blockDim.x + threadIdx.x;           // 0 .. 6*WSZ-1
    const int WSZ = CC * CC;
    int j = i / WSZ, r = i - j * WSZ;
    const float* src = j == 0 ? w0 : j == 1 ? w1 : j == 2 ? w2 : j == 3 ? w3 : j == 4 ? w4 : w5;
    g_wh[i] = __float2half(src[r]);
}

// ---------------- fp16 HMMA GEMM (single product): C = A @ W^T --------------
// CTA tile 128x128, BK=32, 4 warps (2x2), warp tile 64x64, 4-stage cp.async,
// 128 threads, 2 CTAs/SM. Both A and B: 64B rows + 16B pad (ROWA=80).
// EPI: 0 = plain, 1 = sigmoid(x+bias), 2 = qkv (sel 0,1: L2 norm; sel 2: LN).
#define BKK     32
#define ROWA    80
#define ATILE_B (128*ROWA)         // 10240
#define STAGEB  (2*ATILE_B)        // 20480 (A + B)
#define STAGES  4
#define KTILES  (CC/BKK)           // 64
#define GEMM_SMEM (STAGES*STAGEB)  // 81920

template <int EPI>
__global__ void __launch_bounds__(128, 2)
gemm_multi(const __half* __restrict__ Ah,
           const __half* __restrict__ B0, const __half* __restrict__ B1,
           const __half* __restrict__ B2,
           float* __restrict__ C0, float* __restrict__ C1, float* __restrict__ C2,
           const float* __restrict__ bias0, const float* __restrict__ bias1)
{
    extern __shared__ char smem[];
    const uint32_t sb = smem_u32(smem);
    const int sel = blockIdx.x >> 4;
    const __half* Bm = sel == 0 ? B0 : sel == 1 ? B1 : B2;
    float* C = sel == 0 ? C0 : sel == 1 ? C1 : C2;

    const int tid = threadIdx.x;
    const int lane = tid & 31;
    const int wid = tid >> 5;
    const int bm = blockIdx.y * 128;
    const int bn = (blockIdx.x & 15) * 128;
    const int wm = (wid >> 1) * 64;   // 0 or 64
    const int wn = (wid & 1) * 64;    // 0 or 64

    float acc[4][8][4];
#pragma unroll
    for (int i = 0; i < 4; i++)
#pragma unroll
        for (int j = 0; j < 8; j++)
#pragma unroll
            for (int r = 0; r < 4; r++) acc[i][j][r] = 0.f;

    // ldmatrix per-thread address components
    const int arow = lane & 15;
    const uint32_t ahalf = (uint32_t)((lane >> 4) << 4);        // 0 or 16
    const int brow = (lane & 7) | ((lane >> 4) << 3);
    const uint32_t bhalf = (uint32_t)(((lane >> 3) & 1) << 4);  // 0 or 16

    auto load_stage = [&](int s, int kt) {
        uint32_t base = sb + s * STAGEB;
        int k0 = kt * BKK;
#pragma unroll
        for (int i = 0; i < 4; i++) {
            int u = tid + i * 128;          // 0..511
            int r = u >> 2, c = u & 3;
            cp16(base + r * ROWA + c * 16, Ah + (size_t)(bm + r) * CC + k0 + c * 8);
        }
#pragma unroll
        for (int i = 0; i < 4; i++) {
            int u = tid + i * 128;          // 0..511
            int r = u >> 2, c = u & 3;
            cp16(base + ATILE_B + r * ROWA + c * 16, Bm + (size_t)(bn + r) * CC + k0 + c * 8);
        }
    };

    load_stage(0, 0); CP_COMMIT();
    load_stage(1, 1); CP_COMMIT();
    load_stage(2, 2); CP_COMMIT();

    for (int kt = 0; kt < KTILES; kt++) {
        if (kt <= KTILES - 3)      cp_wait<2>();
        else if (kt == KTILES - 2) cp_wait<1>();
        else                       cp_wait<0>();
        __syncthreads();
        if (kt + 3 < KTILES) { load_stage((kt + 3) % STAGES, kt + 3); CP_COMMIT(); }

        const uint32_t st = sb + (kt % STAGES) * STAGEB;
        const uint32_t aBase = st + (uint32_t)((wm + arow) * ROWA);
        const uint32_t bBase = st + ATILE_B + (uint32_t)((wn + brow) * ROWA);
#pragma unroll
        for (int ks = 0; ks < 2; ks++) {
            uint32_t ah[4][4];
            const uint32_t aoff = (uint32_t)(ks * 32) + ahalf;
#pragma unroll
            for (int mi = 0; mi < 4; mi++)
                ldsm4(ah[mi], aBase + mi * 16 * ROWA + aoff);
            const uint32_t boff = (uint32_t)(ks * 32) + bhalf;
#pragma unroll
            for (int jj = 0; jj < 4; jj++) {
                uint32_t bh[4];
                ldsm4(bh, bBase + jj * 16 * ROWA + boff);
#pragma unroll
                for (int mi = 0; mi < 4; mi++) {
                    mma_f16(acc[mi][2*jj],   ah[mi], bh);
                    mma_f16(acc[mi][2*jj+1], ah[mi], bh + 2);
                }
            }
        }
    }

    const int gr = lane >> 2, ti = lane & 3;

    if (EPI == 2) {
        // fused row-norm epilogue: per-row sum/sumsq over the 128-col tile
        float rs[8], rq[8];
#pragma unroll
        for (int mi = 0; mi < 4; mi++) {
#pragma unroll
            for (int half = 0; half < 2; half++) {
                float s = 0.f, ss = 0.f;
#pragma unroll
                for (int j = 0; j < 8; j++) {
                    float a0 = acc[mi][j][half*2+0], a1 = acc[mi][j][half*2+1];
                    s += a0 + a1; ss += a0*a0 + a1*a1;
                }
                rs[mi*2+half] = s; rq[mi*2+half] = ss;
            }
        }
#pragma unroll
        for (int o = 1; o <= 2; o <<= 1) {
#pragma unroll
            for (int t = 0; t < 8; t++) {
                rs[t] += __shfl_xor_sync(0xFFFFFFFFu, rs[t], o);
                rq[t] += __shfl_xor_sync(0xFFFFFFFFu, rq[t], o);
            }
        }
        float* ssum = (float*)smem;         // [128][2]
        float* sss  = ssum + 256;           // [128][2]
        __syncthreads();
        if (ti == 0) {
#pragma unroll
            for (int t = 0; t < 8; t++) {
                int row = wm + (t >> 1) * 16 + (t & 1) * 8 + gr;
                int wc = wid & 1;
                ssum[row * 2 + wc] = rs[t];
                sss [row * 2 + wc] = rq[t];
            }
        }
        __syncthreads();
#pragma unroll
        for (int mi = 0; mi < 4; mi++) {
#pragma unroll
            for (int half = 0; half < 2; half++) {
                int row = wm + mi * 16 + half * 8 + gr;
                int m0 = bm + row;
                float S = ssum[row*2] + ssum[row*2+1];
                float Q = sss [row*2] + sss [row*2+1];
                if (sel < 2) {
                    float inv = 1.f / fmaxf(sqrtf(Q), 1e-12f);
#pragma unroll
                    for (int j = 0; j < 8; j++) {
                        int col = bn + wn + j * 8 + ti * 2;
                        float2 v = make_float2(acc[mi][j][half*2] * inv,
                                               acc[mi][j][half*2+1] * inv);
                        *(float2*)(C + (size_t)m0 * CC + col) = v;
                    }
                } else {
                    float mean = S * (1.f / 128.f);
                    float rr = rsqrtf(Q * (1.f / 128.f) - mean * mean + 1e-5f);
#pragma unroll
                    for (int j = 0; j < 8; j++) {
                        int d = wn + j * 8 + ti * 2;
                        int col = bn + d;
                        float2 v;
                        v.x = (acc[mi][j][half*2]   - mean) * rr * bias0[d]   + bias1[d];
                        v.y = (acc[mi][j][half*2+1] - mean) * rr * bias0[d+1] + bias1[d+1];
                        *(float2*)(C + (size_t)m0 * CC + col) = v;
                    }
                }
            }
        }
    } else {
        const float* bias = (sel == 0) ? bias0 : bias1;
#pragma unroll
        for (int mi = 0; mi < 4; mi++) {
            int m0 = bm + wm + mi * 16 + gr;
#pragma unroll
            for (int j = 0; j < 8; j++) {
                int col = bn + wn + j * 8 + ti * 2;
                float2 v0 = make_float2(acc[mi][j][0], acc[mi][j][1]);
                float2 v1 = make_float2(acc[mi][j][2], acc[mi][j][3]);
                if (EPI == 1) {
                    float b0 = bias[col], b1 = bias[col + 1];
                    v0.x = sigmoidf(v0.x + b0); v0.y = sigmoidf(v0.y + b1);
                    v1.x = sigmoidf(v1.x + b0); v1.y = sigmoidf(v1.y + b1);
                }
                *(float2*)(C + (size_t)m0 * CC + col) = v0;
                *(float2*)(C + (size_t)(m0 + 8) * CC + col) = v1;
            }
        }
    }
}

// ------- causal depthwise conv (K=4) + SiLU + fp16 casts (xc and x) --------
__global__ void conv_silu_kernel(const float* __restrict__ x,
                                 const float* __restrict__ w,
                                 const float* __restrict__ b) {
    int idx = blockIdx.x * blockDim.x + threadIdx.x;
    if (idx >= NTOT) return;
    int c = idx & (CC - 1);
    int t = (idx / CC) & (TT - 1);
    float acc = b[c];
    const float* wc = w + c * KK;
    float xcur = 0.f;
#pragma unroll
    for (int j = 0; j < KK; j++) {
        int tt = t - (KK - 1) + j;
        if (tt >= 0) {
            float xv = x[idx + (j - (KK - 1)) * CC];
            if (j == KK - 1) xcur = xv;
            acc = fmaf(xv, wc[j], acc);
        }
    }
    float y = acc * sigmoidf(acc);
    g_xc[idx] = y;
    g_ch[idx] = __float2half(y);
    g_xh[idx] = __float2half(xcur);
}

// ------- gamma = sigmoid(xc @ gamma_w^T + gamma_b): 8 tokens per block -----
__global__ void gamma_kernel(const float* __restrict__ gw, const float* __restrict__ gb) {
    extern __shared__ float sx[];   // 8*CC floats = 64KB
    int t0 = blockIdx.x * 8;
    for (int i = threadIdx.x; i < 8 * CC; i += 256)
        sx[i] = g_xc[(size_t)t0 * CC + i];
    __syncthreads();
    int warp = threadIdx.x >> 5, lane = threadIdx.x & 31;   // warp = token
    const float* xr = sx + warp * CC;
#pragma unroll
    for (int h = 0; h < HH; h++) {
        const float* w = gw + (size_t)h * CC;
        float s = 0.f;
        for (int k = lane; k < CC; k += 32) s = fmaf(xr[k], w[k], s);
        s = warp_sum(s);
        if (lane == 0) g_gamma[(size_t)(t0 + warp) * HH + h] = sigmoidf(s + gb[h]);
    }
}

// ------- chunked scan pass A: kv = ig*k*v inline + local scan --------------
__global__ void scan_local_kernel() {
    int blk = blockIdx.x;
    int chunk = blk & (NCH - 1);
    int bh = blk / NCH;
    int b = bh / HH, h = bh % HH;
    int d = threadIdx.x;
    int t0 = chunk * CHL;
    size_t idx = ((size_t)(b * TT + t0) * HH + h) * DD + d;
    const float* gam = g_gamma + (size_t)(b * TT + t0) * HH + h;
    float* cumg = g_cumG + (size_t)bh * TT + t0;
    float mem = 0.f, cg = 1.f;
#pragma unroll 4
    for (int tt = 0; tt < CHL; tt++) {
        float g = __ldg(gam + (size_t)tt * HH);
        float kv = g_ig[idx] * g_k[idx] * g_v[idx];
        mem = fmaf(g, mem, kv);
        g_v[idx] = mem;
        cg *= g;
        if (d == 0) cumg[tt] = cg;
        idx += (size_t)HH * DD;
    }
    g_carry[(size_t)blk * DD + d] = mem;
}

// ---------------- chunked scan: pass B (combine carries) -------------------
__global__ void scan_carry_kernel() {
    int bh = blockIdx.x;
    int d = threadIdx.x;
    float p = 0.f;
    for (int c = 0; c < NCH; c++) {
        g_prefix[((size_t)bh * NCH + c) * DD + d] = p;
        float G = g_cumG[(size_t)bh * TT + c * CHL + CHL - 1];
        p = g_carry[((size_t)bh * NCH + c) * DD + d] + G * p;
    }
}

// -------- prefix apply + LN(mem)*q -> GroupNorm -> *og -> fp16 cast --------
__global__ void post_kernel(const float* __restrict__ mn_g, const float* __restrict__ mn_b,
                            const float* __restrict__ gn_g, const float* __restrict__ gn_b) {
    int row = (blockIdx.x * blockDim.x + threadIdx.x) >> 5;
    int lane = threadIdx.x & 31;
    if (row >= NTOK * HH) return;
    size_t off = (size_t)row * DD + lane * 4;
    float4 m  = *(const float4*)(g_v + off);
    float4 q  = *(const float4*)(g_q + off);
    float4 og = *(const float4*)(g_og + off);

    int b = row / (TT * HH);
    int t = (row / HH) & (TT - 1);
    int h = row & (HH - 1);
    int bh = b * HH + h;
    int chunk = t / CHL;
    float cg = g_cumG[(size_t)bh * TT + t];
    float4 pf = *(const float4*)(g_prefix + ((size_t)bh * NCH + chunk) * DD + lane * 4);
    m.x = fmaf(pf.x, cg, m.x);
    m.y = fmaf(pf.y, cg, m.y);
    m.z = fmaf(pf.z, cg, m.z);
    m.w = fmaf(pf.w, cg, m.w);

    float s = m.x + m.y + m.z + m.w;
    float ss = m.x * m.x + m.y * m.y + m.z * m.z + m.w * m.w;
    s = warp_sum(s); ss = warp_sum(ss);
    float mean = s * (1.f / DD);
    float var = ss * (1.f / DD) - mean * mean;
    float r = rsqrtf(var + 1e-5f);
    int d = lane * 4;
    float4 o1;
    o1.x = ((m.x - mean) * r * mn_g[d + 0] + mn_b[d + 0]) * q.x;
    o1.y = ((m.y - mean) * r * mn_g[d + 1] + mn_b[d + 1]) * q.y;
    o1.z = ((m.z - mean) * r * mn_g[d + 2] + mn_b[d + 2]) * q.z;
    o1.w = ((m.w - mean) * r * mn_g[d + 3] + mn_b[d + 3]) * q.w;

    float s2 = o1.x + o1.y + o1.z + o1.w;
    float ss2 = o1.x * o1.x + o1.y * o1.y + o1.z * o1.z + o1.w * o1.w;
    s2 = warp_sum(s2); ss2 = warp_sum(ss2);
    float mean2 = s2 * (1.f / DD);
    float var2 = ss2 * (1.f / DD) - mean2 * mean2;
    float r2 = rsqrtf(var2 + 1e-5f);
    int c = h * DD + d;
    float ov0 = (((o1.x - mean2) * r2) * gn_g[c + 0] + gn_b[c + 0]) * og.x;
    float ov1 = (((o1.y - mean2) * r2) * gn_g[c + 1] + gn_b[c + 1]) * og.y;
    float ov2 = (((o1.z - mean2) * r2) * gn_g[c + 2] + gn_b[c + 2]) * og.z;
    float ov3 = (((o1.w - mean2) * r2) * gn_g[c + 3] + gn_b[c + 3]) * og.w;
    __half2* dst = (__half2*)(g_oh + off);
    dst[0] = __floats2half2_rn(ov0, ov1);
    dst[1] = __floats2half2_rn(ov2, ov3);
}

// ---------------- launch ----------------------------------------------------
extern "C" void kernel_launch(void* const* d_in, const int* in_sizes, int n_in,
                              void* d_out, int out_size) {
    const float* x       = (const float*)d_in[0];
    const float* Wq      = (const float*)d_in[1];
    const float* Wk      = (const float*)d_in[2];
    const float* Wv      = (const float*)d_in[3];
    const float* Wo      = (const float*)d_in[4];
    const float* conv_w  = (const float*)d_in[5];
    const float* conv_b  = (const float*)d_in[6];
    const float* ig_w    = (const float*)d_in[7];
    const float* ig_b    = (const float*)d_in[8];
    const float* og_w    = (const float*)d_in[9];
    const float* og_b    = (const float*)d_in[10];
    const float* gamma_w = (const float*)d_in[11];
    const float* gamma_b = (const float*)d_in[12];
    const float* vn_g    = (const float*)d_in[13];
    const float* vn_b    = (const float*)d_in[14];
    const float* gn_g    = (const float*)d_in[15];
    const float* gn_b    = (const float*)d_in[16];
    const float* mn_g    = (const float*)d_in[17];
    const float* mn_b    = (const float*)d_in[18];
    float* out = (float*)d_out;

    float *p_q, *p_k, *p_v, *p_ig, *p_og;
    cudaGetSymbolAddress((void**)&p_q,  g_q);
    cudaGetSymbolAddress((void**)&p_k,  g_k);
    cudaGetSymbolAddress((void**)&p_v,  g_v);
    cudaGetSymbolAddress((void**)&p_ig, g_ig);
    cudaGetSymbolAddress((void**)&p_og, g_og);

    __half *p_xh, *p_ch, *p_oh, *p_wh;
    cudaGetSymbolAddress((void**)&p_xh, g_xh);
    cudaGetSymbolAddress((void**)&p_ch, g_ch);
    cudaGetSymbolAddress((void**)&p_oh, g_oh);
    cudaGetSymbolAddress((void**)&p_wh, g_wh);

    cudaFuncSetAttribute((const void*)gemm_multi<0>, cudaFuncAttributeMaxDynamicSharedMemorySize, GEMM_SMEM);
    cudaFuncSetAttribute((const void*)gemm_multi<1>, cudaFuncAttributeMaxDynamicSharedMemorySize, GEMM_SMEM);
    cudaFuncSetAttribute((const void*)gemm_multi<2>, cudaFuncAttributeMaxDynamicSharedMemorySize, GEMM_SMEM);
    cudaFuncSetAttribute(gamma_kernel, cudaFuncAttributeMaxDynamicSharedMemorySize, 8 * CC * 4);

    const size_t WSZ = (size_t)CC * CC;   // 4M elems per weight matrix

    // side stream + events for forked capture (created per call; few calls)
    cudaStream_t s1;
    cudaStreamCreateWithFlags(&s1, cudaStreamNonBlocking);
    cudaEvent_t e0, eW, eConv, eJoin;
    cudaEventCreateWithFlags(&e0,    cudaEventDisableTiming);
    cudaEventCreateWithFlags(&eW,    cudaEventDisableTiming);
    cudaEventCreateWithFlags(&eConv, cudaEventDisableTiming);
    cudaEventCreateWithFlags(&eJoin, cudaEventDisableTiming);

    // fork: cvt_w on s1 parallel with conv on default stream
    cudaEventRecord(e0, 0);
    cudaStreamWaitEvent(s1, e0, 0);
    cvt_w_kernel<<<(6 * (int)WSZ) / 256, 256, 0, s1>>>(Wq, Wk, Wv, ig_w, og_w, Wo);
    cudaEventRecord(eW, s1);

    conv_silu_kernel<<<NTOT / 256, 256>>>(x, conv_w, conv_b);
    cudaEventRecord(eConv, 0);

    // qkv on stream 0 (needs conv + cvt_w)
    cudaStreamWaitEvent(0, eW, 0);
    {
        dim3 grid(48, NTOK / 128);
        gemm_multi<2><<<grid, 128, GEMM_SMEM>>>(p_xh,
            p_wh + 0*WSZ, p_wh + 1*WSZ, p_wh + 2*WSZ,
            p_q, p_k, p_v, vn_g, vn_b);
    }

    // ig/og + gamma on s1, overlapping qkv
    cudaStreamWaitEvent(s1, eConv, 0);
    {
        dim3 grid(32, NTOK / 128);
        gemm_multi<1><<<grid, 128, GEMM_SMEM, s1>>>(p_ch,
            p_wh + 3*WSZ, p_wh + 4*WSZ, p_wh + 4*WSZ,
            p_ig, p_og, p_og, ig_b, og_b);
    }
    gamma_kernel<<<NTOK / 8, 256, 8 * CC * 4, s1>>>(gamma_w, gamma_b);
    cudaEventRecord(eJoin, s1);
    cudaStreamWaitEvent(0, eJoin, 0);

    scan_local_kernel<<<BB * HH * NCH, DD>>>();
    scan_carry_kernel<<<BB * HH, DD>>>();

    int nrows = NTOK * HH;                       // 131072 rows of 128
    int rblocks = nrows / 8;
    post_kernel<<<rblocks, 256>>>(mn_g, mn_b, gn_g, gn_b);

    // final projection
    {
        dim3 grid(16, NTOK / 128);
        gemm_multi<0><<<grid, 128, GEMM_SMEM>>>(p_oh,
            p_wh + 5*WSZ, p_wh + 5*WSZ, p_wh + 5*WSZ,
            out, out, out, nullptr, nullptr);
    }
}